// round 3
// baseline (speedup 1.0000x reference)
#include <cuda_runtime.h>
#include <math.h>

// ---------------------------------------------------------------------------
// Problem constants (fixed by setup_inputs)
// ---------------------------------------------------------------------------
#define BWIN    2048
#define N_TOK   49
#define C_DIM   512
#define N_HEADS 16
#define HD      32
#define QKV_N   1536
#define M_ROWS  (BWIN * N_TOK)     // 100352 = 784 * 128
#define NN      (N_TOK * N_TOK)    // 2401
#define NWMASK  64

// ---------------------------------------------------------------------------
// Scratch (static device globals; no runtime allocation allowed)
// ---------------------------------------------------------------------------
__device__ float g_qkv[(size_t)M_ROWS * QKV_N];   // [100352, 1536]
__device__ float g_ao [(size_t)M_ROWS * C_DIM];   // [100352, 512]  attn output, (b,n,h,d)
__device__ float g_pb [N_HEADS * NN];             // 16*sigmoid(bias) pre-gathered [h][n][m]
__device__ float g_qkvbias[QKV_N];                // concat(q_bias, 0, v_bias)

// ---------------------------------------------------------------------------
// Kernel 1: RPE table MLP + bias gather + qkv bias vector
// ---------------------------------------------------------------------------
__device__ __forceinline__ float coord_feat(int x) {
    // t = x * (8/121);  sign(t)*log1p(|t|)/log(8)
    float xs = (float)x * (8.0f / 121.0f);
    float v = log1pf(fabsf(xs)) * 0.48089834696298783f; // 1/ln(8)
    return copysignf(v, xs);
}

__global__ void setup_kernel(const float* __restrict__ rpe_w1,
                             const float* __restrict__ rpe_b1,
                             const float* __restrict__ rpe_w2,
                             const float* __restrict__ q_bias,
                             const float* __restrict__ v_bias) {
    __shared__ float sbt[169 * N_HEADS];
    const int tid = threadIdx.x; // 256 threads

    // Phase A: bias_table[169, 16] = relu(coords @ w1 + b1) @ w2
    if (tid < 169) {
        int a = tid / 13, b = tid % 13;        // row r = a*13 + b
        float c0 = coord_feat(b - 6);          // feature 0 = g(di)
        float c1 = coord_feat(a - 6);          // feature 1 = g(dj)
        float acc[N_HEADS];
        #pragma unroll
        for (int t = 0; t < N_HEADS; t++) acc[t] = 0.f;
        for (int j = 0; j < 512; j++) {
            float h1 = fmaf(c0, rpe_w1[j], fmaf(c1, rpe_w1[512 + j], rpe_b1[j]));
            h1 = fmaxf(h1, 0.f);
            const float* w2 = rpe_w2 + j * N_HEADS;
            #pragma unroll
            for (int t = 0; t < N_HEADS; t++) acc[t] = fmaf(h1, w2[t], acc[t]);
        }
        #pragma unroll
        for (int t = 0; t < N_HEADS; t++) sbt[tid * N_HEADS + t] = acc[t];
    }

    // qkv bias vector: [q_bias, zeros, v_bias]
    for (int c = tid; c < QKV_N; c += 256) {
        float v = 0.f;
        if (c < 512)        v = q_bias[c];
        else if (c >= 1024) v = v_bias[c - 1024];
        g_qkvbias[c] = v;
    }
    __syncthreads();

    // Phase B: g_pb[h][n][m] = 16*sigmoid(bias_table[rel_idx(n,m)][h])
    for (int idx = tid; idx < N_HEADS * NN; idx += 256) {
        int h   = idx / NN;
        int rem = idx % NN;
        int n = rem / N_TOK, m = rem % N_TOK;
        int di = (n / 7) - (m / 7);
        int dj = (n % 7) - (m % 7);
        int r = (dj + 6) * 13 + (di + 6);
        float bt = sbt[r * N_HEADS + h];
        g_pb[idx] = 16.f / (1.f + expf(-bt));
    }
}

// ---------------------------------------------------------------------------
// fp32 SGEMM core: C[M,N] = A[M,K] @ B[K,N] + bias[N]
// BM=BN=128, BK=16, 256 threads, 8x8 per-thread tiles (split 4+4).
// M, N, K are exact multiples (no guards).
// ---------------------------------------------------------------------------
__device__ __forceinline__ void sgemm_core(const float* __restrict__ A,
                                           const float* __restrict__ B,
                                           const float* __restrict__ bias,
                                           float* __restrict__ C,
                                           int N, int K) {
    __shared__ float As[16][132];   // transposed A tile, padded (scalar access only)
    __shared__ float Bs[16][128];

    const int tid = threadIdx.x;
    const int bm = blockIdx.y, bn = blockIdx.x;
    const float* Ablk = A + (size_t)bm * 128 * K;
    const float* Bblk = B + bn * 128;

    const int tr = tid / 16;            // 0..15
    const int tc = tid % 16;            // 0..15
    const int aRow = tid / 4;           // 0..63
    const int aCol = (tid % 4) * 4;     // 0,4,8,12
    const int bRow = tid / 32;          // 0..7
    const int bCol = (tid % 32) * 4;    // 0..124

    float acc[8][8];
    #pragma unroll
    for (int i = 0; i < 8; i++)
        #pragma unroll
        for (int j = 0; j < 8; j++) acc[i][j] = 0.f;

    for (int k0 = 0; k0 < K; k0 += 16) {
        #pragma unroll
        for (int p = 0; p < 2; p++) {
            int r = aRow + p * 64;
            float4 v = *(const float4*)(Ablk + (size_t)r * K + k0 + aCol);
            As[aCol + 0][r] = v.x;
            As[aCol + 1][r] = v.y;
            As[aCol + 2][r] = v.z;
            As[aCol + 3][r] = v.w;
        }
        #pragma unroll
        for (int p = 0; p < 2; p++) {
            int r = bRow + p * 8;
            float4 v = *(const float4*)(Bblk + (size_t)(k0 + r) * N + bCol);
            *(float4*)&Bs[r][bCol] = v;
        }
        __syncthreads();

        #pragma unroll
        for (int kk = 0; kk < 16; kk++) {
            float ra[8], rb[8];
            #pragma unroll
            for (int i = 0; i < 4; i++) {
                ra[i]     = As[kk][tr * 4 + i];
                ra[4 + i] = As[kk][64 + tr * 4 + i];
            }
            #pragma unroll
            for (int j = 0; j < 4; j++) {
                rb[j]     = Bs[kk][tc * 4 + j];
                rb[4 + j] = Bs[kk][64 + tc * 4 + j];
            }
            #pragma unroll
            for (int i = 0; i < 8; i++)
                #pragma unroll
                for (int j = 0; j < 8; j++)
                    acc[i][j] = fmaf(ra[i], rb[j], acc[i][j]);
        }
        __syncthreads();
    }

    #pragma unroll
    for (int i = 0; i < 8; i++) {
        int r = bm * 128 + ((i < 4) ? (tr * 4 + i) : (64 + tr * 4 + (i - 4)));
        #pragma unroll
        for (int jh = 0; jh < 2; jh++) {
            int c = bn * 128 + jh * 64 + tc * 4;
            float4 o;
            o.x = acc[i][jh * 4 + 0] + bias[c + 0];
            o.y = acc[i][jh * 4 + 1] + bias[c + 1];
            o.z = acc[i][jh * 4 + 2] + bias[c + 2];
            o.w = acc[i][jh * 4 + 3] + bias[c + 3];
            *(float4*)(C + (size_t)r * N + c) = o;
        }
    }
}

__global__ void __launch_bounds__(256)
qkv_gemm_kernel(const float* __restrict__ x, const float* __restrict__ qkv_w) {
    sgemm_core(x, qkv_w, g_qkvbias, g_qkv, QKV_N, C_DIM);
}

__global__ void __launch_bounds__(256)
proj_gemm_kernel(const float* __restrict__ proj_w, const float* __restrict__ proj_b,
                 float* __restrict__ out) {
    sgemm_core(g_ao, proj_w, proj_b, out, C_DIM, C_DIM);
}

// ---------------------------------------------------------------------------
// Kernel 3: fused attention per (window, head). Tokens padded 49 -> 64.
// ---------------------------------------------------------------------------
__global__ void __launch_bounds__(256)
attn_kernel(const float* __restrict__ mask, const float* __restrict__ logit_scale) {
    const int b = blockIdx.x >> 4;
    const int h = blockIdx.x & 15;
    const int tid = threadIdx.x;   // 256

    __shared__ float sQ[64][33];
    __shared__ float sK[64][33];
    __shared__ float sV[64][32];   // stride 32: float4-aligned; same-row reads broadcast
    __shared__ float sS[64][65];

    // ---- load q, k, v tiles [49,32], zero-pad to 64 rows ----
    const float* base = g_qkv + (size_t)b * N_TOK * QKV_N + h * HD;
    for (int idx = tid; idx < 64 * 32; idx += 256) {
        int r = idx >> 5, d = idx & 31;
        float qv = 0.f, kv = 0.f, vv = 0.f;
        if (r < N_TOK) {
            const float* p = base + (size_t)r * QKV_N + d;
            qv = p[0];
            kv = p[512];
            vv = p[1024];
        }
        sQ[r][d] = qv;
        sK[r][d] = kv;
        sV[r][d] = vv;
    }
    __syncthreads();

    // ---- l2-normalize rows; fold per-head logit scale into q ----
    if (tid < N_TOK) {
        float s = 0.f;
        #pragma unroll
        for (int d = 0; d < 32; d++) { float v = sQ[tid][d]; s = fmaf(v, v, s); }
        float hs = expf(fminf(logit_scale[h], 4.605170185988091f)); // ln(100)
        float r = rsqrtf(fmaxf(s, 1e-12f)) * hs;
        #pragma unroll
        for (int d = 0; d < 32; d++) sQ[tid][d] *= r;
    } else if (tid >= 64 && tid < 64 + N_TOK) {
        int n = tid - 64;
        float s = 0.f;
        #pragma unroll
        for (int d = 0; d < 32; d++) { float v = sK[n][d]; s = fmaf(v, v, s); }
        float r = rsqrtf(fmaxf(s, 1e-12f));
        #pragma unroll
        for (int d = 0; d < 32; d++) sK[n][d] *= r;
    }
    __syncthreads();

    // ---- S[64,64] = Qn @ Kn^T (4x4 register tiles) ----
    {
        const int tr = tid / 16, tc = tid % 16;
        float acc[4][4];
        #pragma unroll
        for (int i = 0; i < 4; i++)
            #pragma unroll
            for (int j = 0; j < 4; j++) acc[i][j] = 0.f;
        #pragma unroll
        for (int k = 0; k < 32; k++) {
            float ra[4], rb[4];
            #pragma unroll
            for (int i = 0; i < 4; i++) ra[i] = sQ[tr * 4 + i][k];
            #pragma unroll
            for (int j = 0; j < 4; j++) rb[j] = sK[tc * 4 + j][k];
            #pragma unroll
            for (int i = 0; i < 4; i++)
                #pragma unroll
                for (int j = 0; j < 4; j++)
                    acc[i][j] = fmaf(ra[i], rb[j], acc[i][j]);
        }
        #pragma unroll
        for (int i = 0; i < 4; i++)
            #pragma unroll
            for (int j = 0; j < 4; j++)
                sS[tr * 4 + i][tc * 4 + j] = acc[i][j];
    }
    __syncthreads();

    // ---- softmax rows (+pos bias, +mask), zero padded columns ----
    if (tid < N_TOK) {
        const int n = tid;
        const int w = b & (NWMASK - 1);  // b % 64
        const float* pbr = g_pb + h * NN + n * N_TOK;
        const float* mr  = mask + w * NN + n * N_TOK;
        float mx = -1e30f;
        for (int m = 0; m < N_TOK; m++) {
            float s = sS[n][m] + pbr[m] + mr[m];
            sS[n][m] = s;
            mx = fmaxf(mx, s);
        }
        float sum = 0.f;
        for (int m = 0; m < N_TOK; m++) {
            float e = __expf(sS[n][m] - mx);
            sS[n][m] = e;
            sum += e;
        }
        float inv = 1.f / sum;
        for (int m = 0; m < 64; m++)
            sS[n][m] = (m < N_TOK) ? sS[n][m] * inv : 0.f;
    }
    __syncthreads();

    // ---- out[64,32] = P @ V  (2 rows x 4 cols per thread) ----
    {
        const int pr = tid >> 3;          // 0..31
        const int pc = (tid & 7) * 4;     // 0..28
        float o0[4] = {0.f, 0.f, 0.f, 0.f};
        float o1[4] = {0.f, 0.f, 0.f, 0.f};
        #pragma unroll
        for (int m = 0; m < 64; m++) {
            float p0 = sS[pr][m];
            float p1 = sS[32 + pr][m];
            float4 v = *(const float4*)&sV[m][pc];   // 16B-aligned (stride 32 floats)
            o0[0] = fmaf(p0, v.x, o0[0]); o0[1] = fmaf(p0, v.y, o0[1]);
            o0[2] = fmaf(p0, v.z, o0[2]); o0[3] = fmaf(p0, v.w, o0[3]);
            o1[0] = fmaf(p1, v.x, o1[0]); o1[1] = fmaf(p1, v.y, o1[1]);
            o1[2] = fmaf(p1, v.z, o1[2]); o1[3] = fmaf(p1, v.w, o1[3]);
        }
        // ao[b, n, h*32+d]
        float* outp = g_ao + ((size_t)b * N_TOK + pr) * C_DIM + h * HD + pc;
        *(float4*)outp = make_float4(o0[0], o0[1], o0[2], o0[3]);
        if (pr < N_TOK - 32) {  // row 32+pr < 49
            float* outp1 = g_ao + ((size_t)b * N_TOK + 32 + pr) * C_DIM + h * HD + pc;
            *(float4*)outp1 = make_float4(o1[0], o1[1], o1[2], o1[3]);
        }
    }
}

// ---------------------------------------------------------------------------
// Launch
// ---------------------------------------------------------------------------
extern "C" void kernel_launch(void* const* d_in, const int* in_sizes, int n_in,
                              void* d_out, int out_size) {
    const float* x           = (const float*)d_in[0];
    const float* mask        = (const float*)d_in[1];
    const float* qkv_w       = (const float*)d_in[2];
    const float* q_bias      = (const float*)d_in[3];
    const float* v_bias      = (const float*)d_in[4];
    const float* logit_scale = (const float*)d_in[5];
    const float* rpe_w1      = (const float*)d_in[6];
    const float* rpe_b1      = (const float*)d_in[7];
    const float* rpe_w2      = (const float*)d_in[8];
    const float* proj_w      = (const float*)d_in[9];
    const float* proj_b      = (const float*)d_in[10];
    float* out = (float*)d_out;

    setup_kernel<<<1, 256>>>(rpe_w1, rpe_b1, rpe_w2, q_bias, v_bias);

    // QKV: [100352,512] @ [512,1536]
    qkv_gemm_kernel<<<dim3(QKV_N / 128, M_ROWS / 128), 256>>>(x, qkv_w);

    // Attention: one block per (window, head)
    attn_kernel<<<BWIN * N_HEADS, 256>>>(mask, logit_scale);

    // proj: [100352,512] @ [512,512] -> d_out
    proj_gemm_kernel<<<dim3(C_DIM / 128, M_ROWS / 128), 256>>>(proj_w, proj_b, out);
}

// round 4
// speedup vs baseline: 1.0024x; 1.0024x over previous
#include <cuda_runtime.h>
#include <math.h>

// ---------------------------------------------------------------------------
// Problem constants (fixed by setup_inputs)
// ---------------------------------------------------------------------------
#define BWIN    2048
#define N_TOK   49
#define C_DIM   512
#define N_HEADS 16
#define HD      32
#define QKV_N   1536
#define M_ROWS  (BWIN * N_TOK)     // 100352 = 784 * 128
#define NN      (N_TOK * N_TOK)    // 2401
#define NWMASK  64

// ---------------------------------------------------------------------------
// Scratch (static device globals; no runtime allocation allowed)
// ---------------------------------------------------------------------------
__device__ float g_qkv[(size_t)M_ROWS * QKV_N];   // [100352, 1536]
__device__ float g_ao [(size_t)M_ROWS * C_DIM];   // [100352, 512]  attn output, (b,n,h,d)
__device__ float g_pb [N_HEADS * NN];             // 16*sigmoid(bias) pre-gathered [h][n][m]
__device__ float g_qkvbias[QKV_N];                // concat(q_bias, 0, v_bias)

// ---------------------------------------------------------------------------
// Kernel 1: RPE table MLP + bias gather + qkv bias vector
// ---------------------------------------------------------------------------
__device__ __forceinline__ float coord_feat(int x) {
    // t = x * (8/121);  sign(t)*log1p(|t|)/log(8)
    float xs = (float)x * (8.0f / 121.0f);
    float v = log1pf(fabsf(xs)) * 0.48089834696298783f; // 1/ln(8)
    return copysignf(v, xs);
}

__global__ void setup_kernel(const float* __restrict__ rpe_w1,
                             const float* __restrict__ rpe_b1,
                             const float* __restrict__ rpe_w2,
                             const float* __restrict__ q_bias,
                             const float* __restrict__ v_bias) {
    __shared__ float sbt[169 * N_HEADS];
    const int tid = threadIdx.x; // 256 threads

    // Phase A: bias_table[169, 16] = relu(coords @ w1 + b1) @ w2
    if (tid < 169) {
        int a = tid / 13, b = tid % 13;        // row r = a*13 + b
        float c0 = coord_feat(b - 6);          // feature 0 = g(di)
        float c1 = coord_feat(a - 6);          // feature 1 = g(dj)
        float acc[N_HEADS];
        #pragma unroll
        for (int t = 0; t < N_HEADS; t++) acc[t] = 0.f;
        for (int j = 0; j < 512; j++) {
            float h1 = fmaf(c0, rpe_w1[j], fmaf(c1, rpe_w1[512 + j], rpe_b1[j]));
            h1 = fmaxf(h1, 0.f);
            const float* w2 = rpe_w2 + j * N_HEADS;
            #pragma unroll
            for (int t = 0; t < N_HEADS; t++) acc[t] = fmaf(h1, w2[t], acc[t]);
        }
        #pragma unroll
        for (int t = 0; t < N_HEADS; t++) sbt[tid * N_HEADS + t] = acc[t];
    }

    // qkv bias vector: [q_bias, zeros, v_bias]
    for (int c = tid; c < QKV_N; c += 256) {
        float v = 0.f;
        if (c < 512)        v = q_bias[c];
        else if (c >= 1024) v = v_bias[c - 1024];
        g_qkvbias[c] = v;
    }
    __syncthreads();

    // Phase B: g_pb[h][n][m] = 16*sigmoid(bias_table[rel_idx(n,m)][h])
    for (int idx = tid; idx < N_HEADS * NN; idx += 256) {
        int h   = idx / NN;
        int rem = idx % NN;
        int n = rem / N_TOK, m = rem % N_TOK;
        int di = (n / 7) - (m / 7);
        int dj = (n % 7) - (m % 7);
        int r = (dj + 6) * 13 + (di + 6);
        float bt = sbt[r * N_HEADS + h];
        g_pb[idx] = 16.f / (1.f + expf(-bt));
    }
}

// ---------------------------------------------------------------------------
// fp32 SGEMM core: C[M,N] = A[M,K] @ B[K,N] + bias[N]
// BM=BN=128, BK=16, 256 threads, 8x8 per-thread tiles (split 4+4).
// M, N, K are exact multiples (no guards).
// ---------------------------------------------------------------------------
__device__ __forceinline__ void sgemm_core(const float* __restrict__ A,
                                           const float* __restrict__ B,
                                           const float* __restrict__ bias,
                                           float* __restrict__ C,
                                           int N, int K) {
    __shared__ float As[16][132];   // transposed A tile, padded (scalar access only)
    __shared__ float Bs[16][128];

    const int tid = threadIdx.x;
    const int bm = blockIdx.y, bn = blockIdx.x;
    const float* Ablk = A + (size_t)bm * 128 * K;
    const float* Bblk = B + bn * 128;

    const int tr = tid / 16;            // 0..15
    const int tc = tid % 16;            // 0..15
    const int aRow = tid / 4;           // 0..63
    const int aCol = (tid % 4) * 4;     // 0,4,8,12
    const int bRow = tid / 32;          // 0..7
    const int bCol = (tid % 32) * 4;    // 0..124

    float acc[8][8];
    #pragma unroll
    for (int i = 0; i < 8; i++)
        #pragma unroll
        for (int j = 0; j < 8; j++) acc[i][j] = 0.f;

    for (int k0 = 0; k0 < K; k0 += 16) {
        #pragma unroll
        for (int p = 0; p < 2; p++) {
            int r = aRow + p * 64;
            float4 v = *(const float4*)(Ablk + (size_t)r * K + k0 + aCol);
            As[aCol + 0][r] = v.x;
            As[aCol + 1][r] = v.y;
            As[aCol + 2][r] = v.z;
            As[aCol + 3][r] = v.w;
        }
        #pragma unroll
        for (int p = 0; p < 2; p++) {
            int r = bRow + p * 8;
            float4 v = *(const float4*)(Bblk + (size_t)(k0 + r) * N + bCol);
            *(float4*)&Bs[r][bCol] = v;
        }
        __syncthreads();

        #pragma unroll
        for (int kk = 0; kk < 16; kk++) {
            float ra[8], rb[8];
            #pragma unroll
            for (int i = 0; i < 4; i++) {
                ra[i]     = As[kk][tr * 4 + i];
                ra[4 + i] = As[kk][64 + tr * 4 + i];
            }
            #pragma unroll
            for (int j = 0; j < 4; j++) {
                rb[j]     = Bs[kk][tc * 4 + j];
                rb[4 + j] = Bs[kk][64 + tc * 4 + j];
            }
            #pragma unroll
            for (int i = 0; i < 8; i++)
                #pragma unroll
                for (int j = 0; j < 8; j++)
                    acc[i][j] = fmaf(ra[i], rb[j], acc[i][j]);
        }
        __syncthreads();
    }

    #pragma unroll
    for (int i = 0; i < 8; i++) {
        int r = bm * 128 + ((i < 4) ? (tr * 4 + i) : (64 + tr * 4 + (i - 4)));
        #pragma unroll
        for (int jh = 0; jh < 2; jh++) {
            int c = bn * 128 + jh * 64 + tc * 4;
            float4 o;
            o.x = acc[i][jh * 4 + 0] + bias[c + 0];
            o.y = acc[i][jh * 4 + 1] + bias[c + 1];
            o.z = acc[i][jh * 4 + 2] + bias[c + 2];
            o.w = acc[i][jh * 4 + 3] + bias[c + 3];
            *(float4*)(C + (size_t)r * N + c) = o;
        }
    }
}

__global__ void __launch_bounds__(256)
qkv_gemm_kernel(const float* __restrict__ x, const float* __restrict__ qkv_w) {
    sgemm_core(x, qkv_w, g_qkvbias, g_qkv, QKV_N, C_DIM);
}

__global__ void __launch_bounds__(256)
proj_gemm_kernel(const float* __restrict__ proj_w, const float* __restrict__ proj_b,
                 float* __restrict__ out) {
    sgemm_core(g_ao, proj_w, proj_b, out, C_DIM, C_DIM);
}

// ---------------------------------------------------------------------------
// Kernel 3: fused attention per (window, head). Tokens padded 49 -> 64.
// ---------------------------------------------------------------------------
__global__ void __launch_bounds__(256)
attn_kernel(const float* __restrict__ mask, const float* __restrict__ logit_scale) {
    const int b = blockIdx.x >> 4;
    const int h = blockIdx.x & 15;
    const int tid = threadIdx.x;   // 256

    __shared__ float sQ[64][33];
    __shared__ float sK[64][33];
    __shared__ float sV[64][32];   // stride 32: float4-aligned; same-row reads broadcast
    __shared__ float sS[64][65];

    // ---- load q, k, v tiles [49,32], zero-pad to 64 rows ----
    const float* base = g_qkv + (size_t)b * N_TOK * QKV_N + h * HD;
    for (int idx = tid; idx < 64 * 32; idx += 256) {
        int r = idx >> 5, d = idx & 31;
        float qv = 0.f, kv = 0.f, vv = 0.f;
        if (r < N_TOK) {
            const float* p = base + (size_t)r * QKV_N + d;
            qv = p[0];
            kv = p[512];
            vv = p[1024];
        }
        sQ[r][d] = qv;
        sK[r][d] = kv;
        sV[r][d] = vv;
    }
    __syncthreads();

    // ---- l2-normalize rows; fold per-head logit scale into q ----
    if (tid < N_TOK) {
        float s = 0.f;
        #pragma unroll
        for (int d = 0; d < 32; d++) { float v = sQ[tid][d]; s = fmaf(v, v, s); }
        float hs = expf(fminf(logit_scale[h], 4.605170185988091f)); // ln(100)
        float r = rsqrtf(fmaxf(s, 1e-12f)) * hs;
        #pragma unroll
        for (int d = 0; d < 32; d++) sQ[tid][d] *= r;
    } else if (tid >= 64 && tid < 64 + N_TOK) {
        int n = tid - 64;
        float s = 0.f;
        #pragma unroll
        for (int d = 0; d < 32; d++) { float v = sK[n][d]; s = fmaf(v, v, s); }
        float r = rsqrtf(fmaxf(s, 1e-12f));
        #pragma unroll
        for (int d = 0; d < 32; d++) sK[n][d] *= r;
    }
    __syncthreads();

    // ---- S[64,64] = Qn @ Kn^T (4x4 register tiles) ----
    {
        const int tr = tid / 16, tc = tid % 16;
        float acc[4][4];
        #pragma unroll
        for (int i = 0; i < 4; i++)
            #pragma unroll
            for (int j = 0; j < 4; j++) acc[i][j] = 0.f;
        #pragma unroll
        for (int k = 0; k < 32; k++) {
            float ra[4], rb[4];
            #pragma unroll
            for (int i = 0; i < 4; i++) ra[i] = sQ[tr * 4 + i][k];
            #pragma unroll
            for (int j = 0; j < 4; j++) rb[j] = sK[tc * 4 + j][k];
            #pragma unroll
            for (int i = 0; i < 4; i++)
                #pragma unroll
                for (int j = 0; j < 4; j++)
                    acc[i][j] = fmaf(ra[i], rb[j], acc[i][j]);
        }
        #pragma unroll
        for (int i = 0; i < 4; i++)
            #pragma unroll
            for (int j = 0; j < 4; j++)
                sS[tr * 4 + i][tc * 4 + j] = acc[i][j];
    }
    __syncthreads();

    // ---- softmax rows (+pos bias, +mask), zero padded columns ----
    if (tid < N_TOK) {
        const int n = tid;
        const int w = b & (NWMASK - 1);  // b % 64
        const float* pbr = g_pb + h * NN + n * N_TOK;
        const float* mr  = mask + w * NN + n * N_TOK;
        float mx = -1e30f;
        for (int m = 0; m < N_TOK; m++) {
            float s = sS[n][m] + pbr[m] + mr[m];
            sS[n][m] = s;
            mx = fmaxf(mx, s);
        }
        float sum = 0.f;
        for (int m = 0; m < N_TOK; m++) {
            float e = __expf(sS[n][m] - mx);
            sS[n][m] = e;
            sum += e;
        }
        float inv = 1.f / sum;
        for (int m = 0; m < 64; m++)
            sS[n][m] = (m < N_TOK) ? sS[n][m] * inv : 0.f;
    }
    __syncthreads();

    // ---- out[64,32] = P @ V  (2 rows x 4 cols per thread) ----
    {
        const int pr = tid >> 3;          // 0..31
        const int pc = (tid & 7) * 4;     // 0..28
        float o0[4] = {0.f, 0.f, 0.f, 0.f};
        float o1[4] = {0.f, 0.f, 0.f, 0.f};
        #pragma unroll
        for (int m = 0; m < 64; m++) {
            float p0 = sS[pr][m];
            float p1 = sS[32 + pr][m];
            float4 v = *(const float4*)&sV[m][pc];   // 16B-aligned (stride 32 floats)
            o0[0] = fmaf(p0, v.x, o0[0]); o0[1] = fmaf(p0, v.y, o0[1]);
            o0[2] = fmaf(p0, v.z, o0[2]); o0[3] = fmaf(p0, v.w, o0[3]);
            o1[0] = fmaf(p1, v.x, o1[0]); o1[1] = fmaf(p1, v.y, o1[1]);
            o1[2] = fmaf(p1, v.z, o1[2]); o1[3] = fmaf(p1, v.w, o1[3]);
        }
        // ao[b, n, h*32+d]
        float* outp = g_ao + ((size_t)b * N_TOK + pr) * C_DIM + h * HD + pc;
        *(float4*)outp = make_float4(o0[0], o0[1], o0[2], o0[3]);
        if (pr < N_TOK - 32) {  // row 32+pr < 49
            float* outp1 = g_ao + ((size_t)b * N_TOK + 32 + pr) * C_DIM + h * HD + pc;
            *(float4*)outp1 = make_float4(o1[0], o1[1], o1[2], o1[3]);
        }
    }
}

// ---------------------------------------------------------------------------
// Launch
// ---------------------------------------------------------------------------
extern "C" void kernel_launch(void* const* d_in, const int* in_sizes, int n_in,
                              void* d_out, int out_size) {
    const float* x           = (const float*)d_in[0];
    const float* mask        = (const float*)d_in[1];
    const float* qkv_w       = (const float*)d_in[2];
    const float* q_bias      = (const float*)d_in[3];
    const float* v_bias      = (const float*)d_in[4];
    const float* logit_scale = (const float*)d_in[5];
    const float* rpe_w1      = (const float*)d_in[6];
    const float* rpe_b1      = (const float*)d_in[7];
    const float* rpe_w2      = (const float*)d_in[8];
    const float* proj_w      = (const float*)d_in[9];
    const float* proj_b      = (const float*)d_in[10];
    float* out = (float*)d_out;

    setup_kernel<<<1, 256>>>(rpe_w1, rpe_b1, rpe_w2, q_bias, v_bias);

    // QKV: [100352,512] @ [512,1536]
    qkv_gemm_kernel<<<dim3(QKV_N / 128, M_ROWS / 128), 256>>>(x, qkv_w);

    // Attention: one block per (window, head)
    attn_kernel<<<BWIN * N_HEADS, 256>>>(mask, logit_scale);

    // proj: [100352,512] @ [512,512] -> d_out
    proj_gemm_kernel<<<dim3(C_DIM / 128, M_ROWS / 128), 256>>>(proj_w, proj_b, out);
}

// round 7
// speedup vs baseline: 1.5474x; 1.5438x over previous
#include <cuda_runtime.h>
#include <cuda_bf16.h>
#include <math.h>
#include <stdint.h>

// ---------------------------------------------------------------------------
// Problem constants (fixed by setup_inputs)
// ---------------------------------------------------------------------------
#define BWIN    2048
#define N_TOK   49
#define C_DIM   512
#define N_HEADS 16
#define HD      32
#define QKV_N   1536
#define M_ROWS  (BWIN * N_TOK)     // 100352 = 784 * 128
#define NN      (N_TOK * N_TOK)    // 2401
#define NWMASK  64

// ---------------------------------------------------------------------------
// Scratch (static device globals; no runtime allocation allowed)
// ---------------------------------------------------------------------------
__device__ float g_qkv[(size_t)M_ROWS * QKV_N];   // [100352, 1536]
__device__ float g_ao [(size_t)M_ROWS * C_DIM];   // [100352, 512]  attn output, (b,n,h,d)
__device__ float g_pb [N_HEADS * NN];             // 16*sigmoid(bias) pre-gathered [h][n][m]
__device__ float g_qkvbias[QKV_N];                // concat(q_bias, 0, v_bias)

// ---------------------------------------------------------------------------
// Kernel 1: RPE table MLP + bias gather + qkv bias vector
// ---------------------------------------------------------------------------
__device__ __forceinline__ float coord_feat(int x) {
    float xs = (float)x * (8.0f / 121.0f);
    float v = log1pf(fabsf(xs)) * 0.48089834696298783f; // 1/ln(8)
    return copysignf(v, xs);
}

__global__ void setup_kernel(const float* __restrict__ rpe_w1,
                             const float* __restrict__ rpe_b1,
                             const float* __restrict__ rpe_w2,
                             const float* __restrict__ q_bias,
                             const float* __restrict__ v_bias) {
    __shared__ float sbt[169 * N_HEADS];
    const int tid = threadIdx.x; // 256 threads

    if (tid < 169) {
        int a = tid / 13, b = tid % 13;
        float c0 = coord_feat(b - 6);
        float c1 = coord_feat(a - 6);
        float acc[N_HEADS];
        #pragma unroll
        for (int t = 0; t < N_HEADS; t++) acc[t] = 0.f;
        for (int j = 0; j < 512; j++) {
            float h1 = fmaf(c0, rpe_w1[j], fmaf(c1, rpe_w1[512 + j], rpe_b1[j]));
            h1 = fmaxf(h1, 0.f);
            const float* w2 = rpe_w2 + j * N_HEADS;
            #pragma unroll
            for (int t = 0; t < N_HEADS; t++) acc[t] = fmaf(h1, w2[t], acc[t]);
        }
        #pragma unroll
        for (int t = 0; t < N_HEADS; t++) sbt[tid * N_HEADS + t] = acc[t];
    }

    for (int c = tid; c < QKV_N; c += 256) {
        float v = 0.f;
        if (c < 512)        v = q_bias[c];
        else if (c >= 1024) v = v_bias[c - 1024];
        g_qkvbias[c] = v;
    }
    __syncthreads();

    for (int idx = tid; idx < N_HEADS * NN; idx += 256) {
        int h   = idx / NN;
        int rem = idx % NN;
        int n = rem / N_TOK, m = rem % N_TOK;
        int di = (n / 7) - (m / 7);
        int dj = (n % 7) - (m % 7);
        int r = (dj + 6) * 13 + (di + 6);
        float bt = sbt[r * N_HEADS + h];
        g_pb[idx] = 16.f / (1.f + expf(-bt));
    }
}

// ---------------------------------------------------------------------------
// Split-bf16 tensor-core GEMM: C[M,N] = A[M,K] @ B[K,N] + bias[N]
// A,B fp32 in gmem; each split into bf16 hi+lo; D = Ah*Bh + Ah*Bl + Al*Bh
// (effective ~18-bit input precision, fp32 accumulate).
// BM=BN=128, BK=32, 256 threads = 8 warps, each warp 64x32 (m16n8k16 tiles).
// M % 128 == 0, N % 128 == 0, K % 32 == 0 (all hold here).
// ---------------------------------------------------------------------------
#define SA_STRIDE 40   // bf16 elems per row: conflict-free fragment loads
#define SB_STRIDE 34   // conflict-free transpose stores

__device__ __forceinline__ void mma_bf16(float d[4],
                                         const uint32_t a[4],
                                         const uint32_t b[2]) {
    asm volatile(
        "mma.sync.aligned.m16n8k16.row.col.f32.bf16.bf16.f32 "
        "{%0,%1,%2,%3}, {%4,%5,%6,%7}, {%8,%9}, {%0,%1,%2,%3};\n"
        : "+f"(d[0]), "+f"(d[1]), "+f"(d[2]), "+f"(d[3])
        : "r"(a[0]), "r"(a[1]), "r"(a[2]), "r"(a[3]), "r"(b[0]), "r"(b[1]));
}

__device__ __forceinline__ uint32_t pack2(__nv_bfloat16 a, __nv_bfloat16 b) {
    __nv_bfloat162 v; v.x = a; v.y = b;
    return *(uint32_t*)&v;
}

__device__ __forceinline__ void split1(float v, __nv_bfloat16& h, __nv_bfloat16& l) {
    h = __float2bfloat16(v);
    l = __float2bfloat16(v - __bfloat162float(h));
}

__device__ __forceinline__ void gemm_core_bf16(const float* __restrict__ A,
                                               const float* __restrict__ B,
                                               const float* __restrict__ bias,
                                               float* __restrict__ C,
                                               int N, int K) {
    __shared__ __nv_bfloat16 sAh[128][SA_STRIDE];
    __shared__ __nv_bfloat16 sAl[128][SA_STRIDE];
    __shared__ __nv_bfloat16 sBh[128][SB_STRIDE];
    __shared__ __nv_bfloat16 sBl[128][SB_STRIDE];

    const int tid  = threadIdx.x;
    const int bm   = blockIdx.y, bn = blockIdx.x;
    const int lane = tid & 31;
    const int w    = tid >> 5;
    const int wm   = (w >> 2) * 64;       // 0 or 64
    const int wn   = (w & 3) * 32;        // 0,32,64,96
    const int g    = lane >> 2;           // 0..7
    const int t2   = (lane & 3) * 2;      // 0,2,4,6

    const float* Ablk = A + (size_t)bm * 128 * K;
    const float* Bblk = B + bn * 128;

    // staging assignments
    const int ar  = tid >> 3;             // 0..31 (A row within group of 32)
    const int ac  = (tid & 7) * 4;        // 0..28 (A k-col, float4)
    const int bn_ = tid & 127;            // B column (n) handled by this thread
    const int bk  = (tid >> 7) * 16;      // k half: 0 or 16

    float4 stA[4];
    float  stB[16];

    float acc[4][4][4];
    #pragma unroll
    for (int mi = 0; mi < 4; mi++)
        #pragma unroll
        for (int ni = 0; ni < 4; ni++)
            #pragma unroll
            for (int r = 0; r < 4; r++) acc[mi][ni][r] = 0.f;

    const int iters = K / 32;

    // prefetch iter 0
    #pragma unroll
    for (int p = 0; p < 4; p++)
        stA[p] = *(const float4*)(Ablk + (size_t)(p * 32 + ar) * K + ac);
    #pragma unroll
    for (int i = 0; i < 16; i++)
        stB[i] = Bblk[(size_t)(bk + i) * N + bn_];

    for (int it = 0; it < iters; it++) {
        __syncthreads();   // smem consumers of previous iter done

        // store staged A (split hi/lo, pack pairs of k)
        #pragma unroll
        for (int p = 0; p < 4; p++) {
            int row = p * 32 + ar;
            __nv_bfloat16 hx, lx, hy, ly, hz, lz, hw, lw;
            split1(stA[p].x, hx, lx);
            split1(stA[p].y, hy, ly);
            split1(stA[p].z, hz, lz);
            split1(stA[p].w, hw, lw);
            *(uint32_t*)&sAh[row][ac]     = pack2(hx, hy);
            *(uint32_t*)&sAh[row][ac + 2] = pack2(hz, hw);
            *(uint32_t*)&sAl[row][ac]     = pack2(lx, ly);
            *(uint32_t*)&sAl[row][ac + 2] = pack2(lz, lw);
        }
        // store staged B transposed to [n][k]
        #pragma unroll
        for (int i = 0; i < 8; i++) {
            int k = bk + 2 * i;
            __nv_bfloat16 h0, l0, h1, l1;
            split1(stB[2 * i],     h0, l0);
            split1(stB[2 * i + 1], h1, l1);
            *(uint32_t*)&sBh[bn_][k] = pack2(h0, h1);
            *(uint32_t*)&sBl[bn_][k] = pack2(l0, l1);
        }
        __syncthreads();

        // prefetch next iter (overlaps with compute below)
        if (it + 1 < iters) {
            int kk = (it + 1) * 32;
            #pragma unroll
            for (int p = 0; p < 4; p++)
                stA[p] = *(const float4*)(Ablk + (size_t)(p * 32 + ar) * K + kk + ac);
            #pragma unroll
            for (int i = 0; i < 16; i++)
                stB[i] = Bblk[(size_t)(kk + bk + i) * N + bn_];
        }

        // compute: 2 k16 steps
        #pragma unroll
        for (int ks = 0; ks < 32; ks += 16) {
            uint32_t ah[4][4], al[4][4];
            #pragma unroll
            for (int mi = 0; mi < 4; mi++) {
                int m = wm + mi * 16 + g;
                ah[mi][0] = *(const uint32_t*)&sAh[m][ks + t2];
                ah[mi][1] = *(const uint32_t*)&sAh[m + 8][ks + t2];
                ah[mi][2] = *(const uint32_t*)&sAh[m][ks + t2 + 8];
                ah[mi][3] = *(const uint32_t*)&sAh[m + 8][ks + t2 + 8];
                al[mi][0] = *(const uint32_t*)&sAl[m][ks + t2];
                al[mi][1] = *(const uint32_t*)&sAl[m + 8][ks + t2];
                al[mi][2] = *(const uint32_t*)&sAl[m][ks + t2 + 8];
                al[mi][3] = *(const uint32_t*)&sAl[m + 8][ks + t2 + 8];
            }
            uint32_t bh[4][2], bl[4][2];
            #pragma unroll
            for (int ni = 0; ni < 4; ni++) {
                int n = wn + ni * 8 + g;
                bh[ni][0] = *(const uint32_t*)&sBh[n][ks + t2];
                bh[ni][1] = *(const uint32_t*)&sBh[n][ks + t2 + 8];
                bl[ni][0] = *(const uint32_t*)&sBl[n][ks + t2];
                bl[ni][1] = *(const uint32_t*)&sBl[n][ks + t2 + 8];
            }
            #pragma unroll
            for (int mi = 0; mi < 4; mi++)
                #pragma unroll
                for (int ni = 0; ni < 4; ni++) {
                    mma_bf16(acc[mi][ni], ah[mi], bh[ni]);
                    mma_bf16(acc[mi][ni], ah[mi], bl[ni]);
                    mma_bf16(acc[mi][ni], al[mi], bh[ni]);
                }
        }
    }

    // epilogue
    #pragma unroll
    for (int mi = 0; mi < 4; mi++) {
        int row = bm * 128 + wm + mi * 16 + g;
        #pragma unroll
        for (int ni = 0; ni < 4; ni++) {
            int col = bn * 128 + wn + ni * 8 + t2;
            float b0 = bias[col], b1 = bias[col + 1];
            float2 o0 = make_float2(acc[mi][ni][0] + b0, acc[mi][ni][1] + b1);
            float2 o1 = make_float2(acc[mi][ni][2] + b0, acc[mi][ni][3] + b1);
            *(float2*)(C + (size_t)row * N + col)       = o0;
            *(float2*)(C + (size_t)(row + 8) * N + col) = o1;
        }
    }
}

__global__ void __launch_bounds__(256, 1)
qkv_gemm_kernel(const float* __restrict__ x, const float* __restrict__ qkv_w) {
    gemm_core_bf16(x, qkv_w, g_qkvbias, g_qkv, QKV_N, C_DIM);
}

__global__ void __launch_bounds__(256, 1)
proj_gemm_kernel(const float* __restrict__ proj_w, const float* __restrict__ proj_b,
                 float* __restrict__ out) {
    gemm_core_bf16(g_ao, proj_w, proj_b, out, C_DIM, C_DIM);
}

// ---------------------------------------------------------------------------
// Kernel 3: fused attention per (window, head). Tokens padded 49 -> 64.
// ---------------------------------------------------------------------------
__global__ void __launch_bounds__(256)
attn_kernel(const float* __restrict__ mask, const float* __restrict__ logit_scale) {
    const int b = blockIdx.x >> 4;
    const int h = blockIdx.x & 15;
    const int tid = threadIdx.x;   // 256

    __shared__ float sQ[64][33];
    __shared__ float sK[64][33];
    __shared__ float sV[64][32];   // stride 32: float4-aligned; same-row reads broadcast
    __shared__ float sS[64][65];

    const float* base = g_qkv + (size_t)b * N_TOK * QKV_N + h * HD;
    for (int idx = tid; idx < 64 * 32; idx += 256) {
        int r = idx >> 5, d = idx & 31;
        float qv = 0.f, kv = 0.f, vv = 0.f;
        if (r < N_TOK) {
            const float* p = base + (size_t)r * QKV_N + d;
            qv = p[0];
            kv = p[512];
            vv = p[1024];
        }
        sQ[r][d] = qv;
        sK[r][d] = kv;
        sV[r][d] = vv;
    }
    __syncthreads();

    if (tid < N_TOK) {
        float s = 0.f;
        #pragma unroll
        for (int d = 0; d < 32; d++) { float v = sQ[tid][d]; s = fmaf(v, v, s); }
        float hs = expf(fminf(logit_scale[h], 4.605170185988091f)); // ln(100)
        float r = rsqrtf(fmaxf(s, 1e-12f)) * hs;
        #pragma unroll
        for (int d = 0; d < 32; d++) sQ[tid][d] *= r;
    } else if (tid >= 64 && tid < 64 + N_TOK) {
        int n = tid - 64;
        float s = 0.f;
        #pragma unroll
        for (int d = 0; d < 32; d++) { float v = sK[n][d]; s = fmaf(v, v, s); }
        float r = rsqrtf(fmaxf(s, 1e-12f));
        #pragma unroll
        for (int d = 0; d < 32; d++) sK[n][d] *= r;
    }
    __syncthreads();

    {
        const int tr = tid / 16, tc = tid % 16;
        float acc[4][4];
        #pragma unroll
        for (int i = 0; i < 4; i++)
            #pragma unroll
            for (int j = 0; j < 4; j++) acc[i][j] = 0.f;
        #pragma unroll
        for (int k = 0; k < 32; k++) {
            float ra[4], rb[4];
            #pragma unroll
            for (int i = 0; i < 4; i++) ra[i] = sQ[tr * 4 + i][k];
            #pragma unroll
            for (int j = 0; j < 4; j++) rb[j] = sK[tc * 4 + j][k];
            #pragma unroll
            for (int i = 0; i < 4; i++)
                #pragma unroll
                for (int j = 0; j < 4; j++)
                    acc[i][j] = fmaf(ra[i], rb[j], acc[i][j]);
        }
        #pragma unroll
        for (int i = 0; i < 4; i++)
            #pragma unroll
            for (int j = 0; j < 4; j++)
                sS[tr * 4 + i][tc * 4 + j] = acc[i][j];
    }
    __syncthreads();

    if (tid < N_TOK) {
        const int n = tid;
        const int w = b & (NWMASK - 1);  // b % 64
        const float* pbr = g_pb + h * NN + n * N_TOK;
        const float* mr  = mask + w * NN + n * N_TOK;
        float mx = -1e30f;
        for (int m = 0; m < N_TOK; m++) {
            float s = sS[n][m] + pbr[m] + mr[m];
            sS[n][m] = s;
            mx = fmaxf(mx, s);
        }
        float sum = 0.f;
        for (int m = 0; m < N_TOK; m++) {
            float e = __expf(sS[n][m] - mx);
            sS[n][m] = e;
            sum += e;
        }
        float inv = 1.f / sum;
        for (int m = 0; m < 64; m++)
            sS[n][m] = (m < N_TOK) ? sS[n][m] * inv : 0.f;
    }
    __syncthreads();

    {
        const int pr = tid >> 3;          // 0..31
        const int pc = (tid & 7) * 4;     // 0..28
        float o0[4] = {0.f, 0.f, 0.f, 0.f};
        float o1[4] = {0.f, 0.f, 0.f, 0.f};
        #pragma unroll
        for (int m = 0; m < 64; m++) {
            float p0 = sS[pr][m];
            float p1 = sS[32 + pr][m];
            float4 v = *(const float4*)&sV[m][pc];
            o0[0] = fmaf(p0, v.x, o0[0]); o0[1] = fmaf(p0, v.y, o0[1]);
            o0[2] = fmaf(p0, v.z, o0[2]); o0[3] = fmaf(p0, v.w, o0[3]);
            o1[0] = fmaf(p1, v.x, o1[0]); o1[1] = fmaf(p1, v.y, o1[1]);
            o1[2] = fmaf(p1, v.z, o1[2]); o1[3] = fmaf(p1, v.w, o1[3]);
        }
        float* outp = g_ao + ((size_t)b * N_TOK + pr) * C_DIM + h * HD + pc;
        *(float4*)outp = make_float4(o0[0], o0[1], o0[2], o0[3]);
        if (pr < N_TOK - 32) {
            float* outp1 = g_ao + ((size_t)b * N_TOK + 32 + pr) * C_DIM + h * HD + pc;
            *(float4*)outp1 = make_float4(o1[0], o1[1], o1[2], o1[3]);
        }
    }
}

// ---------------------------------------------------------------------------
// Launch
// ---------------------------------------------------------------------------
extern "C" void kernel_launch(void* const* d_in, const int* in_sizes, int n_in,
                              void* d_out, int out_size) {
    const float* x           = (const float*)d_in[0];
    const float* mask        = (const float*)d_in[1];
    const float* qkv_w       = (const float*)d_in[2];
    const float* q_bias      = (const float*)d_in[3];
    const float* v_bias      = (const float*)d_in[4];
    const float* logit_scale = (const float*)d_in[5];
    const float* rpe_w1      = (const float*)d_in[6];
    const float* rpe_b1      = (const float*)d_in[7];
    const float* rpe_w2      = (const float*)d_in[8];
    const float* proj_w      = (const float*)d_in[9];
    const float* proj_b      = (const float*)d_in[10];
    float* out = (float*)d_out;

    setup_kernel<<<1, 256>>>(rpe_w1, rpe_b1, rpe_w2, q_bias, v_bias);

    // QKV: [100352,512] @ [512,1536]
    qkv_gemm_kernel<<<dim3(QKV_N / 128, M_ROWS / 128), 256>>>(x, qkv_w);

    // Attention: one block per (window, head)
    attn_kernel<<<BWIN * N_HEADS, 256>>>(mask, logit_scale);

    // proj: [100352,512] @ [512,512] -> d_out
    proj_gemm_kernel<<<dim3(C_DIM / 128, M_ROWS / 128), 256>>>(proj_w, proj_b, out);
}

// round 8
// speedup vs baseline: 1.8434x; 1.1913x over previous
#include <cuda_runtime.h>
#include <cuda_bf16.h>
#include <math.h>
#include <stdint.h>

// ---------------------------------------------------------------------------
// Problem constants
// ---------------------------------------------------------------------------
#define BWIN    2048
#define N_TOK   49
#define C_DIM   512
#define N_HEADS 16
#define HD      32
#define QKV_N   1536
#define M_ROWS  (BWIN * N_TOK)     // 100352 = 784 * 128
#define NN      (N_TOK * N_TOK)    // 2401
#define NWMASK  64

// ---------------------------------------------------------------------------
// Scratch (static device globals)
// ---------------------------------------------------------------------------
__device__ float g_qkv[(size_t)M_ROWS * QKV_N];          // fp32 qkv
__device__ __nv_bfloat16 g_xh[(size_t)M_ROWS * C_DIM];   // x split hi
__device__ __nv_bfloat16 g_xl[(size_t)M_ROWS * C_DIM];   // x split lo
__device__ __nv_bfloat16 g_aoh[(size_t)M_ROWS * C_DIM];  // attn out split hi
__device__ __nv_bfloat16 g_aol[(size_t)M_ROWS * C_DIM];  // attn out split lo
__device__ __nv_bfloat16 g_qwh[C_DIM * QKV_N];
__device__ __nv_bfloat16 g_qwl[C_DIM * QKV_N];
__device__ __nv_bfloat16 g_pwh[C_DIM * C_DIM];
__device__ __nv_bfloat16 g_pwl[C_DIM * C_DIM];
__device__ float g_pb [N_HEADS * NN];
__device__ float g_qkvbias[QKV_N];

// ---------------------------------------------------------------------------
// Helpers
// ---------------------------------------------------------------------------
__device__ __forceinline__ uint32_t pack2(__nv_bfloat16 a, __nv_bfloat16 b) {
    __nv_bfloat162 v; v.x = a; v.y = b;
    return *(uint32_t*)&v;
}
__device__ __forceinline__ void split1(float v, __nv_bfloat16& h, __nv_bfloat16& l) {
    h = __float2bfloat16(v);
    l = __float2bfloat16(v - __bfloat162float(h));
}

__device__ __forceinline__ void mma_bf16(float d[4],
                                         const uint32_t a[4],
                                         const uint32_t b[2]) {
    asm volatile(
        "mma.sync.aligned.m16n8k16.row.col.f32.bf16.bf16.f32 "
        "{%0,%1,%2,%3}, {%4,%5,%6,%7}, {%8,%9}, {%0,%1,%2,%3};\n"
        : "+f"(d[0]), "+f"(d[1]), "+f"(d[2]), "+f"(d[3])
        : "r"(a[0]), "r"(a[1]), "r"(a[2]), "r"(a[3]), "r"(b[0]), "r"(b[1]));
}
__device__ __forceinline__ void ldsm_x4(uint32_t r[4], uint32_t addr) {
    asm volatile("ldmatrix.sync.aligned.m8n8.x4.shared.b16 {%0,%1,%2,%3}, [%4];\n"
                 : "=r"(r[0]), "=r"(r[1]), "=r"(r[2]), "=r"(r[3]) : "r"(addr));
}
__device__ __forceinline__ void ldsm_x2t(uint32_t r[2], uint32_t addr) {
    asm volatile("ldmatrix.sync.aligned.m8n8.x2.trans.shared.b16 {%0,%1}, [%2];\n"
                 : "=r"(r[0]), "=r"(r[1]) : "r"(addr));
}
__device__ __forceinline__ void cp16(uint32_t dst, const void* src) {
    asm volatile("cp.async.cg.shared.global [%0], [%1], 16;\n" :: "r"(dst), "l"(src));
}
__device__ __forceinline__ void cp_commit() { asm volatile("cp.async.commit_group;\n"); }
__device__ __forceinline__ void cp_wait1()  { asm volatile("cp.async.wait_group 1;\n" ::: "memory"); }

// ---------------------------------------------------------------------------
// Split kernel: fp32 -> bf16 hi/lo (vectorized x4)
// ---------------------------------------------------------------------------
__global__ void split_kernel(const float* __restrict__ src,
                             __nv_bfloat16* __restrict__ dh,
                             __nv_bfloat16* __restrict__ dl, int n4) {
    int i = blockIdx.x * blockDim.x + threadIdx.x;
    if (i >= n4) return;
    float4 v = ((const float4*)src)[i];
    __nv_bfloat16 hx, lx, hy, ly, hz, lz, hw, lw;
    split1(v.x, hx, lx); split1(v.y, hy, ly);
    split1(v.z, hz, lz); split1(v.w, hw, lw);
    uint2 ph, pl;
    ph.x = pack2(hx, hy); ph.y = pack2(hz, hw);
    pl.x = pack2(lx, ly); pl.y = pack2(lz, lw);
    ((uint2*)dh)[i] = ph;
    ((uint2*)dl)[i] = pl;
}

// ---------------------------------------------------------------------------
// Kernel 1: RPE table MLP + bias gather + qkv bias vector
// ---------------------------------------------------------------------------
__device__ __forceinline__ float coord_feat(int x) {
    float xs = (float)x * (8.0f / 121.0f);
    float v = log1pf(fabsf(xs)) * 0.48089834696298783f; // 1/ln(8)
    return copysignf(v, xs);
}

__global__ void setup_kernel(const float* __restrict__ rpe_w1,
                             const float* __restrict__ rpe_b1,
                             const float* __restrict__ rpe_w2,
                             const float* __restrict__ q_bias,
                             const float* __restrict__ v_bias) {
    __shared__ float sbt[169 * N_HEADS];
    const int tid = threadIdx.x; // 256 threads

    if (tid < 169) {
        int a = tid / 13, b = tid % 13;
        float c0 = coord_feat(b - 6);
        float c1 = coord_feat(a - 6);
        float acc[N_HEADS];
        #pragma unroll
        for (int t = 0; t < N_HEADS; t++) acc[t] = 0.f;
        for (int j = 0; j < 512; j++) {
            float h1 = fmaf(c0, rpe_w1[j], fmaf(c1, rpe_w1[512 + j], rpe_b1[j]));
            h1 = fmaxf(h1, 0.f);
            const float* w2 = rpe_w2 + j * N_HEADS;
            #pragma unroll
            for (int t = 0; t < N_HEADS; t++) acc[t] = fmaf(h1, w2[t], acc[t]);
        }
        #pragma unroll
        for (int t = 0; t < N_HEADS; t++) sbt[tid * N_HEADS + t] = acc[t];
    }

    for (int c = tid; c < QKV_N; c += 256) {
        float v = 0.f;
        if (c < 512)        v = q_bias[c];
        else if (c >= 1024) v = v_bias[c - 1024];
        g_qkvbias[c] = v;
    }
    __syncthreads();

    for (int idx = tid; idx < N_HEADS * NN; idx += 256) {
        int h   = idx / NN;
        int rem = idx % NN;
        int n = rem / N_TOK, m = rem % N_TOK;
        int di = (n / 7) - (m / 7);
        int dj = (n % 7) - (m % 7);
        int r = (dj + 6) * 13 + (di + 6);
        float bt = sbt[r * N_HEADS + h];
        g_pb[idx] = 16.f / (1.f + expf(-bt));
    }
}

// ---------------------------------------------------------------------------
// Pipelined split-bf16 tensor-core GEMM.
// A (hi/lo) [M,K] bf16 row-major, B (hi/lo) [K,N] bf16 row-major.
// C[M,N] = (Ah+Al)@(Bh+Bl) + bias  ~= Ah*Bh + Ah*Bl + Al*Bh  (fp32 accum)
// BM=BN=128, BK=32, 256 threads = 8 warps (each 64x32).
// cp.async double-buffered, ldmatrix fragment loads.
// ---------------------------------------------------------------------------
#define SA_STR 40    // A smem row stride (bf16): 80B, 16B-aligned, conflict-free ldsm
#define SB_STR 136   // B smem row stride (bf16): 272B, 16B-aligned, conflict-free ldsm
#define ASIZE (128 * SA_STR)   // 5120 elems per buffer
#define BSIZE (32 * SB_STR)    // 4352 elems per buffer
#define SMEM_BYTES ((2 * (2 * ASIZE + 2 * BSIZE)) * 2)  // 75776 B

__device__ __forceinline__ void gemm_issue(
    int it, int buf, int iters, int tid,
    const __nv_bfloat16* Ah, const __nv_bfloat16* Al,
    const __nv_bfloat16* Bh, const __nv_bfloat16* Bl,
    size_t Abase, int nblk, int N, int K,
    uint32_t sAh32, uint32_t sAl32, uint32_t sBh32, uint32_t sBl32)
{
    if (it < iters) {
        const int k0 = it * 32;
        const uint32_t aoff = (uint32_t)buf * (ASIZE * 2);
        const uint32_t boff = (uint32_t)buf * (BSIZE * 2);
        #pragma unroll
        for (int p = 0; p < 2; p++) {
            int c = tid + p * 256;
            int row = c >> 2, seg = (c & 3) * 8;
            size_t go = Abase + (size_t)row * K + k0 + seg;
            uint32_t ds = (uint32_t)(row * SA_STR + seg) * 2;
            cp16(sAh32 + aoff + ds, Ah + go);
            cp16(sAl32 + aoff + ds, Al + go);
        }
        #pragma unroll
        for (int p = 0; p < 2; p++) {
            int c = tid + p * 256;
            int row = c >> 4, seg = (c & 15) * 8;
            size_t go = (size_t)(k0 + row) * N + nblk + seg;
            uint32_t ds = (uint32_t)(row * SB_STR + seg) * 2;
            cp16(sBh32 + boff + ds, Bh + go);
            cp16(sBl32 + boff + ds, Bl + go);
        }
    }
    cp_commit();   // commit every iteration (empty groups keep the count uniform)
}

__device__ __forceinline__ void gemm_core(
    const __nv_bfloat16* __restrict__ Ah, const __nv_bfloat16* __restrict__ Al,
    const __nv_bfloat16* __restrict__ Bh, const __nv_bfloat16* __restrict__ Bl,
    const float* __restrict__ bias, float* __restrict__ C, int N, int K)
{
    extern __shared__ __nv_bfloat16 smem[];
    __nv_bfloat16* sAh = smem;
    __nv_bfloat16* sAl = sAh + 2 * ASIZE;
    __nv_bfloat16* sBh = sAl + 2 * ASIZE;
    __nv_bfloat16* sBl = sBh + 2 * BSIZE;

    const int tid  = threadIdx.x;
    const int bm   = blockIdx.y, bn = blockIdx.x;
    const int lane = tid & 31;
    const int w    = tid >> 5;
    const int wm   = (w >> 2) * 64;
    const int wn   = (w & 3) * 32;
    const int l15  = lane & 15;
    const int lhi8 = (lane >> 4) * 8;

    const size_t Abase = (size_t)bm * 128 * K;
    const int nblk = bn * 128;

    const uint32_t sAh32 = (uint32_t)__cvta_generic_to_shared(sAh);
    const uint32_t sAl32 = (uint32_t)__cvta_generic_to_shared(sAl);
    const uint32_t sBh32 = (uint32_t)__cvta_generic_to_shared(sBh);
    const uint32_t sBl32 = (uint32_t)__cvta_generic_to_shared(sBl);

    float acc[4][4][4];
    #pragma unroll
    for (int mi = 0; mi < 4; mi++)
        #pragma unroll
        for (int ni = 0; ni < 4; ni++)
            #pragma unroll
            for (int r = 0; r < 4; r++) acc[mi][ni][r] = 0.f;

    const int iters = K / 32;
    gemm_issue(0, 0, iters, tid, Ah, Al, Bh, Bl, Abase, nblk, N, K, sAh32, sAl32, sBh32, sBl32);
    gemm_issue(1, 1, iters, tid, Ah, Al, Bh, Bl, Abase, nblk, N, K, sAh32, sAl32, sBh32, sBl32);

    for (int it = 0; it < iters; it++) {
        const int buf = it & 1;
        cp_wait1();
        __syncthreads();

        const uint32_t aoff = (uint32_t)buf * (ASIZE * 2);
        const uint32_t boff = (uint32_t)buf * (BSIZE * 2);

        #pragma unroll
        for (int ks = 0; ks < 32; ks += 16) {
            // B fragments: ldmatrix.x2.trans on [k][n] rows
            uint32_t bh[4][2], bl[4][2];
            #pragma unroll
            for (int ni = 0; ni < 4; ni++) {
                uint32_t ds = (uint32_t)((ks + l15) * SB_STR + wn + ni * 8) * 2;
                ldsm_x2t(bh[ni], sBh32 + boff + ds);
                ldsm_x2t(bl[ni], sBl32 + boff + ds);
            }
            // A fragments + MMAs
            #pragma unroll
            for (int mi = 0; mi < 4; mi++) {
                uint32_t ds = (uint32_t)((wm + mi * 16 + l15) * SA_STR + ks + lhi8) * 2;
                uint32_t ah[4], al[4];
                ldsm_x4(ah, sAh32 + aoff + ds);
                ldsm_x4(al, sAl32 + aoff + ds);
                #pragma unroll
                for (int ni = 0; ni < 4; ni++) {
                    mma_bf16(acc[mi][ni], ah, bh[ni]);
                    mma_bf16(acc[mi][ni], ah, bl[ni]);
                    mma_bf16(acc[mi][ni], al, bh[ni]);
                }
            }
        }
        __syncthreads();
        gemm_issue(it + 2, buf, iters, tid, Ah, Al, Bh, Bl, Abase, nblk, N, K,
                   sAh32, sAl32, sBh32, sBl32);
    }

    // epilogue
    const int g  = lane >> 2;
    const int t2 = (lane & 3) * 2;
    #pragma unroll
    for (int mi = 0; mi < 4; mi++) {
        int row = bm * 128 + wm + mi * 16 + g;
        #pragma unroll
        for (int ni = 0; ni < 4; ni++) {
            int col = bn * 128 + wn + ni * 8 + t2;
            float b0 = bias[col], b1 = bias[col + 1];
            float2 o0 = make_float2(acc[mi][ni][0] + b0, acc[mi][ni][1] + b1);
            float2 o1 = make_float2(acc[mi][ni][2] + b0, acc[mi][ni][3] + b1);
            *(float2*)(C + (size_t)row * N + col)       = o0;
            *(float2*)(C + (size_t)(row + 8) * N + col) = o1;
        }
    }
}

__global__ void __launch_bounds__(256, 2)
qkv_gemm_kernel() {
    gemm_core(g_xh, g_xl, g_qwh, g_qwl, g_qkvbias, g_qkv, QKV_N, C_DIM);
}

__global__ void __launch_bounds__(256, 2)
proj_gemm_kernel(const float* __restrict__ proj_b, float* __restrict__ out) {
    gemm_core(g_aoh, g_aol, g_pwh, g_pwl, proj_b, out, C_DIM, C_DIM);
}

// ---------------------------------------------------------------------------
// Kernel 3: fused attention per (window, head). Tokens padded 49 -> 64.
// Epilogue writes split bf16 hi/lo for the proj GEMM.
// ---------------------------------------------------------------------------
__global__ void __launch_bounds__(256)
attn_kernel(const float* __restrict__ mask, const float* __restrict__ logit_scale) {
    const int b = blockIdx.x >> 4;
    const int h = blockIdx.x & 15;
    const int tid = threadIdx.x;   // 256

    __shared__ float sQ[64][33];
    __shared__ float sK[64][33];
    __shared__ float sV[64][32];
    __shared__ float sS[64][65];

    const float* base = g_qkv + (size_t)b * N_TOK * QKV_N + h * HD;
    for (int idx = tid; idx < 64 * 32; idx += 256) {
        int r = idx >> 5, d = idx & 31;
        float qv = 0.f, kv = 0.f, vv = 0.f;
        if (r < N_TOK) {
            const float* p = base + (size_t)r * QKV_N + d;
            qv = p[0];
            kv = p[512];
            vv = p[1024];
        }
        sQ[r][d] = qv;
        sK[r][d] = kv;
        sV[r][d] = vv;
    }
    __syncthreads();

    if (tid < N_TOK) {
        float s = 0.f;
        #pragma unroll
        for (int d = 0; d < 32; d++) { float v = sQ[tid][d]; s = fmaf(v, v, s); }
        float hs = expf(fminf(logit_scale[h], 4.605170185988091f)); // ln(100)
        float r = rsqrtf(fmaxf(s, 1e-12f)) * hs;
        #pragma unroll
        for (int d = 0; d < 32; d++) sQ[tid][d] *= r;
    } else if (tid >= 64 && tid < 64 + N_TOK) {
        int n = tid - 64;
        float s = 0.f;
        #pragma unroll
        for (int d = 0; d < 32; d++) { float v = sK[n][d]; s = fmaf(v, v, s); }
        float r = rsqrtf(fmaxf(s, 1e-12f));
        #pragma unroll
        for (int d = 0; d < 32; d++) sK[n][d] *= r;
    }
    __syncthreads();

    {
        const int tr = tid / 16, tc = tid % 16;
        float acc[4][4];
        #pragma unroll
        for (int i = 0; i < 4; i++)
            #pragma unroll
            for (int j = 0; j < 4; j++) acc[i][j] = 0.f;
        #pragma unroll
        for (int k = 0; k < 32; k++) {
            float ra[4], rb[4];
            #pragma unroll
            for (int i = 0; i < 4; i++) ra[i] = sQ[tr * 4 + i][k];
            #pragma unroll
            for (int j = 0; j < 4; j++) rb[j] = sK[tc * 4 + j][k];
            #pragma unroll
            for (int i = 0; i < 4; i++)
                #pragma unroll
                for (int j = 0; j < 4; j++)
                    acc[i][j] = fmaf(ra[i], rb[j], acc[i][j]);
        }
        #pragma unroll
        for (int i = 0; i < 4; i++)
            #pragma unroll
            for (int j = 0; j < 4; j++)
                sS[tr * 4 + i][tc * 4 + j] = acc[i][j];
    }
    __syncthreads();

    if (tid < N_TOK) {
        const int n = tid;
        const int w = b & (NWMASK - 1);
        const float* pbr = g_pb + h * NN + n * N_TOK;
        const float* mr  = mask + w * NN + n * N_TOK;
        float mx = -1e30f;
        for (int m = 0; m < N_TOK; m++) {
            float s = sS[n][m] + pbr[m] + mr[m];
            sS[n][m] = s;
            mx = fmaxf(mx, s);
        }
        float sum = 0.f;
        for (int m = 0; m < N_TOK; m++) {
            float e = __expf(sS[n][m] - mx);
            sS[n][m] = e;
            sum += e;
        }
        float inv = 1.f / sum;
        for (int m = 0; m < 64; m++)
            sS[n][m] = (m < N_TOK) ? sS[n][m] * inv : 0.f;
    }
    __syncthreads();

    {
        const int pr = tid >> 3;          // 0..31
        const int pc = (tid & 7) * 4;     // 0..28
        float o0[4] = {0.f, 0.f, 0.f, 0.f};
        float o1[4] = {0.f, 0.f, 0.f, 0.f};
        #pragma unroll
        for (int m = 0; m < 64; m++) {
            float p0 = sS[pr][m];
            float p1 = sS[32 + pr][m];
            float4 v = *(const float4*)&sV[m][pc];
            o0[0] = fmaf(p0, v.x, o0[0]); o0[1] = fmaf(p0, v.y, o0[1]);
            o0[2] = fmaf(p0, v.z, o0[2]); o0[3] = fmaf(p0, v.w, o0[3]);
            o1[0] = fmaf(p1, v.x, o1[0]); o1[1] = fmaf(p1, v.y, o1[1]);
            o1[2] = fmaf(p1, v.z, o1[2]); o1[3] = fmaf(p1, v.w, o1[3]);
        }
        // split-store to g_aoh/g_aol at [b, n, h*32+d]
        size_t idx0 = ((size_t)b * N_TOK + pr) * C_DIM + h * HD + pc;
        {
            __nv_bfloat16 h0,l0,h1,l1,h2,l2,h3,l3;
            split1(o0[0], h0, l0); split1(o0[1], h1, l1);
            split1(o0[2], h2, l2); split1(o0[3], h3, l3);
            uint2 ph, pl;
            ph.x = pack2(h0, h1); ph.y = pack2(h2, h3);
            pl.x = pack2(l0, l1); pl.y = pack2(l2, l3);
            *(uint2*)(g_aoh + idx0) = ph;
            *(uint2*)(g_aol + idx0) = pl;
        }
        if (pr < N_TOK - 32) {
            size_t idx1 = ((size_t)b * N_TOK + 32 + pr) * C_DIM + h * HD + pc;
            __nv_bfloat16 h0,l0,h1,l1,h2,l2,h3,l3;
            split1(o1[0], h0, l0); split1(o1[1], h1, l1);
            split1(o1[2], h2, l2); split1(o1[3], h3, l3);
            uint2 ph, pl;
            ph.x = pack2(h0, h1); ph.y = pack2(h2, h3);
            pl.x = pack2(l0, l1); pl.y = pack2(l2, l3);
            *(uint2*)(g_aoh + idx1) = ph;
            *(uint2*)(g_aol + idx1) = pl;
        }
    }
}

// ---------------------------------------------------------------------------
// Launch
// ---------------------------------------------------------------------------
extern "C" void kernel_launch(void* const* d_in, const int* in_sizes, int n_in,
                              void* d_out, int out_size) {
    const float* x           = (const float*)d_in[0];
    const float* mask        = (const float*)d_in[1];
    const float* qkv_w       = (const float*)d_in[2];
    const float* q_bias      = (const float*)d_in[3];
    const float* v_bias      = (const float*)d_in[4];
    const float* logit_scale = (const float*)d_in[5];
    const float* rpe_w1      = (const float*)d_in[6];
    const float* rpe_b1      = (const float*)d_in[7];
    const float* rpe_w2      = (const float*)d_in[8];
    const float* proj_w      = (const float*)d_in[9];
    const float* proj_b      = (const float*)d_in[10];
    float* out = (float*)d_out;

    cudaFuncSetAttribute(qkv_gemm_kernel,
                         cudaFuncAttributeMaxDynamicSharedMemorySize, SMEM_BYTES);
    cudaFuncSetAttribute(proj_gemm_kernel,
                         cudaFuncAttributeMaxDynamicSharedMemorySize, SMEM_BYTES);

    // resolve device-global addresses for split targets
    __nv_bfloat16 *xh, *xl, *qwh, *qwl, *pwh, *pwl;
    cudaGetSymbolAddress((void**)&xh,  g_xh);
    cudaGetSymbolAddress((void**)&xl,  g_xl);
    cudaGetSymbolAddress((void**)&qwh, g_qwh);
    cudaGetSymbolAddress((void**)&qwl, g_qwl);
    cudaGetSymbolAddress((void**)&pwh, g_pwh);
    cudaGetSymbolAddress((void**)&pwl, g_pwl);

    setup_kernel<<<1, 256>>>(rpe_w1, rpe_b1, rpe_w2, q_bias, v_bias);

    // pre-split operands to bf16 hi/lo
    {
        int n4 = M_ROWS * C_DIM / 4;
        split_kernel<<<(n4 + 255) / 256, 256>>>(x, xh, xl, n4);
    }
    {
        int n4 = C_DIM * QKV_N / 4;
        split_kernel<<<(n4 + 255) / 256, 256>>>(qkv_w, qwh, qwl, n4);
    }
    {
        int n4 = C_DIM * C_DIM / 4;
        split_kernel<<<(n4 + 255) / 256, 256>>>(proj_w, pwh, pwl, n4);
    }

    // QKV: [100352,512] @ [512,1536]
    qkv_gemm_kernel<<<dim3(QKV_N / 128, M_ROWS / 128), 256, SMEM_BYTES>>>();

    // Attention: one block per (window, head); writes split bf16 output
    attn_kernel<<<BWIN * N_HEADS, 256>>>(mask, logit_scale);

    // proj: [100352,512] @ [512,512] -> d_out
    proj_gemm_kernel<<<dim3(C_DIM / 128, M_ROWS / 128), 256, SMEM_BYTES>>>(proj_b, out);
}

// round 10
// speedup vs baseline: 2.1644x; 1.1742x over previous
#include <cuda_runtime.h>
#include <cuda_bf16.h>
#include <math.h>
#include <stdint.h>

// ---------------------------------------------------------------------------
// Problem constants
// ---------------------------------------------------------------------------
#define BWIN    2048
#define N_TOK   49
#define C_DIM   512
#define N_HEADS 16
#define HD      32
#define QKV_N   1536
#define M_ROWS  (BWIN * N_TOK)     // 100352 = 784 * 128
#define NN      (N_TOK * N_TOK)    // 2401
#define NWMASK  64

// ---------------------------------------------------------------------------
// Scratch (static device globals)
// ---------------------------------------------------------------------------
__device__ float g_qkv[(size_t)M_ROWS * QKV_N];          // fp32 qkv
__device__ __nv_bfloat16 g_xh[(size_t)M_ROWS * C_DIM];   // x split hi
__device__ __nv_bfloat16 g_xl[(size_t)M_ROWS * C_DIM];   // x split lo
__device__ __nv_bfloat16 g_aoh[(size_t)M_ROWS * C_DIM];  // attn out split hi
__device__ __nv_bfloat16 g_aol[(size_t)M_ROWS * C_DIM];  // attn out split lo
__device__ __nv_bfloat16 g_qwh[C_DIM * QKV_N];
__device__ __nv_bfloat16 g_qwl[C_DIM * QKV_N];
__device__ __nv_bfloat16 g_pwh[C_DIM * C_DIM];
__device__ __nv_bfloat16 g_pwl[C_DIM * C_DIM];
__device__ float g_pb [N_HEADS * NN];
__device__ float g_qkvbias[QKV_N];

// ---------------------------------------------------------------------------
// Helpers
// ---------------------------------------------------------------------------
__device__ __forceinline__ uint32_t pack2(__nv_bfloat16 a, __nv_bfloat16 b) {
    __nv_bfloat162 v; v.x = a; v.y = b;
    return *(uint32_t*)&v;
}
__device__ __forceinline__ void split1(float v, __nv_bfloat16& h, __nv_bfloat16& l) {
    h = __float2bfloat16(v);
    l = __float2bfloat16(v - __bfloat162float(h));
}

__device__ __forceinline__ void mma_bf16(float d[4],
                                         const uint32_t a[4],
                                         const uint32_t b[2]) {
    asm volatile(
        "mma.sync.aligned.m16n8k16.row.col.f32.bf16.bf16.f32 "
        "{%0,%1,%2,%3}, {%4,%5,%6,%7}, {%8,%9}, {%0,%1,%2,%3};\n"
        : "+f"(d[0]), "+f"(d[1]), "+f"(d[2]), "+f"(d[3])
        : "r"(a[0]), "r"(a[1]), "r"(a[2]), "r"(a[3]), "r"(b[0]), "r"(b[1]));
}
__device__ __forceinline__ void ldsm_x4(uint32_t r[4], uint32_t addr) {
    asm volatile("ldmatrix.sync.aligned.m8n8.x4.shared.b16 {%0,%1,%2,%3}, [%4];\n"
                 : "=r"(r[0]), "=r"(r[1]), "=r"(r[2]), "=r"(r[3]) : "r"(addr));
}
__device__ __forceinline__ void ldsm_x2t(uint32_t r[2], uint32_t addr) {
    asm volatile("ldmatrix.sync.aligned.m8n8.x2.trans.shared.b16 {%0,%1}, [%2];\n"
                 : "=r"(r[0]), "=r"(r[1]) : "r"(addr));
}
__device__ __forceinline__ void cp16(uint32_t dst, const void* src) {
    asm volatile("cp.async.cg.shared.global [%0], [%1], 16;\n" :: "r"(dst), "l"(src));
}
__device__ __forceinline__ void cp_commit() { asm volatile("cp.async.commit_group;\n"); }
__device__ __forceinline__ void cp_wait1()  { asm volatile("cp.async.wait_group 1;\n" ::: "memory"); }

// ---------------------------------------------------------------------------
// Split kernel: fp32 -> bf16 hi/lo (vectorized x4)
// ---------------------------------------------------------------------------
__global__ void split_kernel(const float* __restrict__ src,
                             __nv_bfloat16* __restrict__ dh,
                             __nv_bfloat16* __restrict__ dl, int n4) {
    int i = blockIdx.x * blockDim.x + threadIdx.x;
    if (i >= n4) return;
    float4 v = ((const float4*)src)[i];
    __nv_bfloat16 hx, lx, hy, ly, hz, lz, hw, lw;
    split1(v.x, hx, lx); split1(v.y, hy, ly);
    split1(v.z, hz, lz); split1(v.w, hw, lw);
    uint2 ph, pl;
    ph.x = pack2(hx, hy); ph.y = pack2(hz, hw);
    pl.x = pack2(lx, ly); pl.y = pack2(lz, lw);
    ((uint2*)dh)[i] = ph;
    ((uint2*)dl)[i] = pl;
}

// ---------------------------------------------------------------------------
// Kernel 1: RPE table MLP + bias gather + qkv bias vector
// ---------------------------------------------------------------------------
__device__ __forceinline__ float coord_feat(int x) {
    float xs = (float)x * (8.0f / 121.0f);
    float v = log1pf(fabsf(xs)) * 0.48089834696298783f; // 1/ln(8)
    return copysignf(v, xs);
}

__global__ void setup_kernel(const float* __restrict__ rpe_w1,
                             const float* __restrict__ rpe_b1,
                             const float* __restrict__ rpe_w2,
                             const float* __restrict__ q_bias,
                             const float* __restrict__ v_bias) {
    __shared__ float sbt[169 * N_HEADS];
    const int tid = threadIdx.x; // 256 threads

    if (tid < 169) {
        int a = tid / 13, b = tid % 13;
        float c0 = coord_feat(b - 6);
        float c1 = coord_feat(a - 6);
        float acc[N_HEADS];
        #pragma unroll
        for (int t = 0; t < N_HEADS; t++) acc[t] = 0.f;
        for (int j = 0; j < 512; j++) {
            float h1 = fmaf(c0, rpe_w1[j], fmaf(c1, rpe_w1[512 + j], rpe_b1[j]));
            h1 = fmaxf(h1, 0.f);
            const float* w2 = rpe_w2 + j * N_HEADS;
            #pragma unroll
            for (int t = 0; t < N_HEADS; t++) acc[t] = fmaf(h1, w2[t], acc[t]);
        }
        #pragma unroll
        for (int t = 0; t < N_HEADS; t++) sbt[tid * N_HEADS + t] = acc[t];
    }

    for (int c = tid; c < QKV_N; c += 256) {
        float v = 0.f;
        if (c < 512)        v = q_bias[c];
        else if (c >= 1024) v = v_bias[c - 1024];
        g_qkvbias[c] = v;
    }
    __syncthreads();

    for (int idx = tid; idx < N_HEADS * NN; idx += 256) {
        int h   = idx / NN;
        int rem = idx % NN;
        int n = rem / N_TOK, m = rem % N_TOK;
        int di = (n / 7) - (m / 7);
        int dj = (n % 7) - (m % 7);
        int r = (dj + 6) * 13 + (di + 6);
        float bt = sbt[r * N_HEADS + h];
        g_pb[idx] = 16.f / (1.f + expf(-bt));
    }
}

// ---------------------------------------------------------------------------
// Pipelined split-bf16 tensor-core GEMM (unchanged; validated R8)
// ---------------------------------------------------------------------------
#define SA_STR 40
#define SB_STR 136
#define ASIZE (128 * SA_STR)
#define BSIZE (32 * SB_STR)
#define SMEM_BYTES ((2 * (2 * ASIZE + 2 * BSIZE)) * 2)  // 75776 B

__device__ __forceinline__ void gemm_issue(
    int it, int buf, int iters, int tid,
    const __nv_bfloat16* Ah, const __nv_bfloat16* Al,
    const __nv_bfloat16* Bh, const __nv_bfloat16* Bl,
    size_t Abase, int nblk, int N, int K,
    uint32_t sAh32, uint32_t sAl32, uint32_t sBh32, uint32_t sBl32)
{
    if (it < iters) {
        const int k0 = it * 32;
        const uint32_t aoff = (uint32_t)buf * (ASIZE * 2);
        const uint32_t boff = (uint32_t)buf * (BSIZE * 2);
        #pragma unroll
        for (int p = 0; p < 2; p++) {
            int c = tid + p * 256;
            int row = c >> 2, seg = (c & 3) * 8;
            size_t go = Abase + (size_t)row * K + k0 + seg;
            uint32_t ds = (uint32_t)(row * SA_STR + seg) * 2;
            cp16(sAh32 + aoff + ds, Ah + go);
            cp16(sAl32 + aoff + ds, Al + go);
        }
        #pragma unroll
        for (int p = 0; p < 2; p++) {
            int c = tid + p * 256;
            int row = c >> 4, seg = (c & 15) * 8;
            size_t go = (size_t)(k0 + row) * N + nblk + seg;
            uint32_t ds = (uint32_t)(row * SB_STR + seg) * 2;
            cp16(sBh32 + boff + ds, Bh + go);
            cp16(sBl32 + boff + ds, Bl + go);
        }
    }
    cp_commit();
}

__device__ __forceinline__ void gemm_core(
    const __nv_bfloat16* __restrict__ Ah, const __nv_bfloat16* __restrict__ Al,
    const __nv_bfloat16* __restrict__ Bh, const __nv_bfloat16* __restrict__ Bl,
    const float* __restrict__ bias, float* __restrict__ C, int N, int K)
{
    extern __shared__ __nv_bfloat16 smem[];
    __nv_bfloat16* sAh = smem;
    __nv_bfloat16* sAl = sAh + 2 * ASIZE;
    __nv_bfloat16* sBh = sAl + 2 * ASIZE;
    __nv_bfloat16* sBl = sBh + 2 * BSIZE;

    const int tid  = threadIdx.x;
    const int bm   = blockIdx.y, bn = blockIdx.x;
    const int lane = tid & 31;
    const int w    = tid >> 5;
    const int wm   = (w >> 2) * 64;
    const int wn   = (w & 3) * 32;
    const int l15  = lane & 15;
    const int lhi8 = (lane >> 4) * 8;

    const size_t Abase = (size_t)bm * 128 * K;
    const int nblk = bn * 128;

    const uint32_t sAh32 = (uint32_t)__cvta_generic_to_shared(sAh);
    const uint32_t sAl32 = (uint32_t)__cvta_generic_to_shared(sAl);
    const uint32_t sBh32 = (uint32_t)__cvta_generic_to_shared(sBh);
    const uint32_t sBl32 = (uint32_t)__cvta_generic_to_shared(sBl);

    float acc[4][4][4];
    #pragma unroll
    for (int mi = 0; mi < 4; mi++)
        #pragma unroll
        for (int ni = 0; ni < 4; ni++)
            #pragma unroll
            for (int r = 0; r < 4; r++) acc[mi][ni][r] = 0.f;

    const int iters = K / 32;
    gemm_issue(0, 0, iters, tid, Ah, Al, Bh, Bl, Abase, nblk, N, K, sAh32, sAl32, sBh32, sBl32);
    gemm_issue(1, 1, iters, tid, Ah, Al, Bh, Bl, Abase, nblk, N, K, sAh32, sAl32, sBh32, sBl32);

    for (int it = 0; it < iters; it++) {
        const int buf = it & 1;
        cp_wait1();
        __syncthreads();

        const uint32_t aoff = (uint32_t)buf * (ASIZE * 2);
        const uint32_t boff = (uint32_t)buf * (BSIZE * 2);

        #pragma unroll
        for (int ks = 0; ks < 32; ks += 16) {
            uint32_t bh[4][2], bl[4][2];
            #pragma unroll
            for (int ni = 0; ni < 4; ni++) {
                uint32_t ds = (uint32_t)((ks + l15) * SB_STR + wn + ni * 8) * 2;
                ldsm_x2t(bh[ni], sBh32 + boff + ds);
                ldsm_x2t(bl[ni], sBl32 + boff + ds);
            }
            #pragma unroll
            for (int mi = 0; mi < 4; mi++) {
                uint32_t ds = (uint32_t)((wm + mi * 16 + l15) * SA_STR + ks + lhi8) * 2;
                uint32_t ah[4], al[4];
                ldsm_x4(ah, sAh32 + aoff + ds);
                ldsm_x4(al, sAl32 + aoff + ds);
                #pragma unroll
                for (int ni = 0; ni < 4; ni++) {
                    mma_bf16(acc[mi][ni], ah, bh[ni]);
                    mma_bf16(acc[mi][ni], ah, bl[ni]);
                    mma_bf16(acc[mi][ni], al, bh[ni]);
                }
            }
        }
        __syncthreads();
        gemm_issue(it + 2, buf, iters, tid, Ah, Al, Bh, Bl, Abase, nblk, N, K,
                   sAh32, sAl32, sBh32, sBl32);
    }

    const int g  = lane >> 2;
    const int t2 = (lane & 3) * 2;
    #pragma unroll
    for (int mi = 0; mi < 4; mi++) {
        int row = bm * 128 + wm + mi * 16 + g;
        #pragma unroll
        for (int ni = 0; ni < 4; ni++) {
            int col = bn * 128 + wn + ni * 8 + t2;
            float b0 = bias[col], b1 = bias[col + 1];
            float2 o0 = make_float2(acc[mi][ni][0] + b0, acc[mi][ni][1] + b1);
            float2 o1 = make_float2(acc[mi][ni][2] + b0, acc[mi][ni][3] + b1);
            *(float2*)(C + (size_t)row * N + col)       = o0;
            *(float2*)(C + (size_t)(row + 8) * N + col) = o1;
        }
    }
}

__global__ void __launch_bounds__(256, 2)
qkv_gemm_kernel() {
    gemm_core(g_xh, g_xl, g_qwh, g_qwl, g_qkvbias, g_qkv, QKV_N, C_DIM);
}

__global__ void __launch_bounds__(256, 2)
proj_gemm_kernel(const float* __restrict__ proj_b, float* __restrict__ out) {
    gemm_core(g_aoh, g_aol, g_pwh, g_pwl, proj_b, out, C_DIM, C_DIM);
}

// ---------------------------------------------------------------------------
// Kernel 3: tensor-core attention per (window, head), split-bf16 3-term MMAs.
// Tokens padded 49 -> 64. 256 threads = 8 warps.
// Phase 4 is fully UNIFORM (no divergent shfl): padded rows compute garbage
// softmax values that only reach discarded output rows (>= N_TOK).
// ---------------------------------------------------------------------------
#define ATT_QH  0
#define ATT_QL  5120
#define ATT_KTH 10240
#define ATT_KTL 14848
#define ATT_VH  19456
#define ATT_VL  24576
#define ATT_SS  29696
#define ATT_TOT (29696 + 64 * 66 * 4)   // 46592 B
#define ATT_PH  0
#define ATT_PL  9216

__global__ void __launch_bounds__(256, 2)
attn_kernel(const float* __restrict__ mask, const float* __restrict__ logit_scale) {
    const int b = blockIdx.x >> 4;
    const int h = blockIdx.x & 15;
    const int tid  = threadIdx.x;
    const int lane = tid & 31;
    const int w    = tid >> 5;

    __shared__ __align__(16) char sm[ATT_TOT];
    __nv_bfloat16* sQh  = (__nv_bfloat16*)(sm + ATT_QH);
    __nv_bfloat16* sQl  = (__nv_bfloat16*)(sm + ATT_QL);
    __nv_bfloat16* sKth = (__nv_bfloat16*)(sm + ATT_KTH);
    __nv_bfloat16* sKtl = (__nv_bfloat16*)(sm + ATT_KTL);
    __nv_bfloat16* sVh  = (__nv_bfloat16*)(sm + ATT_VH);
    __nv_bfloat16* sVl  = (__nv_bfloat16*)(sm + ATT_VL);
    __nv_bfloat16* sPh  = (__nv_bfloat16*)(sm + ATT_PH);
    __nv_bfloat16* sPl  = (__nv_bfloat16*)(sm + ATT_PL);
    float* sS = (float*)(sm + ATT_SS);
    const uint32_t smb = (uint32_t)__cvta_generic_to_shared(sm);

    // ---- Phase 1: load q,k fp32 into staging; v split directly ----
    const float* base = g_qkv + (size_t)b * N_TOK * QKV_N + h * HD;
    #pragma unroll
    for (int p = 0; p < 8; p++) {
        int idx = tid + p * 256;          // 0..2047 covers 64x32
        int r = idx >> 5, d = idx & 31;
        float qv = 0.f, kv = 0.f, vv = 0.f;
        if (r < N_TOK) {
            const float* pp = base + (size_t)r * QKV_N + d;
            qv = pp[0]; kv = pp[512]; vv = pp[1024];
        }
        sS[r * 66 + d]      = qv;
        sS[r * 66 + 32 + d] = kv;
        __nv_bfloat16 vh, vl;
        split1(vv, vh, vl);
        sVh[r * 40 + d] = vh;
        sVl[r * 40 + d] = vl;
    }
    __syncthreads();

    // ---- Phase 2: normalize rows (4 threads/row, uniform), split Q / K^T ----
    {
        const int r  = tid >> 2;          // 0..63
        const int qd = (tid & 3) * 8;     // 0,8,16,24
        float qv[8], kv[8];
        float sq = 0.f, sk = 0.f;
        #pragma unroll
        for (int j = 0; j < 8; j++) {
            qv[j] = sS[r * 66 + qd + j];
            kv[j] = sS[r * 66 + 32 + qd + j];
            sq = fmaf(qv[j], qv[j], sq);
            sk = fmaf(kv[j], kv[j], sk);
        }
        sq += __shfl_xor_sync(0xffffffff, sq, 1);
        sq += __shfl_xor_sync(0xffffffff, sq, 2);
        sk += __shfl_xor_sync(0xffffffff, sk, 1);
        sk += __shfl_xor_sync(0xffffffff, sk, 2);
        float hs  = __expf(fminf(logit_scale[h], 4.605170185988091f));
        float qsc = rsqrtf(fmaxf(sq, 1e-12f)) * hs;
        float ksc = rsqrtf(fmaxf(sk, 1e-12f));
        #pragma unroll
        for (int j = 0; j < 8; j += 2) {
            __nv_bfloat16 h0, l0, h1, l1;
            split1(qv[j] * qsc, h0, l0);
            split1(qv[j + 1] * qsc, h1, l1);
            *(uint32_t*)&sQh[r * 40 + qd + j] = pack2(h0, h1);
            *(uint32_t*)&sQl[r * 40 + qd + j] = pack2(l0, l1);
        }
        #pragma unroll
        for (int j = 0; j < 8; j++) {
            __nv_bfloat16 kh, kl;
            split1(kv[j] * ksc, kh, kl);
            sKth[(qd + j) * 72 + r] = kh;   // transposed [dim][token]
            sKtl[(qd + j) * 72 + r] = kl;
        }
    }
    __syncthreads();

    // ---- Phase 3: S = Qn @ Kn^T via 3-term split-bf16 MMA ----
    {
        const int m0  = (w & 3) * 16;
        const int n0  = (w >> 2) * 32;
        const int l15 = lane & 15;
        const int lhi8 = (lane >> 4) * 8;
        float acc[4][4];
        #pragma unroll
        for (int ni = 0; ni < 4; ni++)
            #pragma unroll
            for (int r = 0; r < 4; r++) acc[ni][r] = 0.f;

        #pragma unroll
        for (int ks = 0; ks < 32; ks += 16) {
            uint32_t ah[4], al[4];
            uint32_t dsA = (uint32_t)(ATT_QH) + (uint32_t)((m0 + l15) * 40 + ks + lhi8) * 2;
            ldsm_x4(ah, smb + dsA);
            ldsm_x4(al, smb + dsA + (ATT_QL - ATT_QH));
            #pragma unroll
            for (int ni = 0; ni < 4; ni++) {
                uint32_t bh[2], bl[2];
                uint32_t dsB = (uint32_t)(ATT_KTH) + (uint32_t)((ks + l15) * 72 + n0 + ni * 8) * 2;
                ldsm_x2t(bh, smb + dsB);
                ldsm_x2t(bl, smb + dsB + (ATT_KTL - ATT_KTH));
                mma_bf16(acc[ni], ah, bh);
                mma_bf16(acc[ni], ah, bl);
                mma_bf16(acc[ni], al, bh);
            }
        }
        const int g  = lane >> 2;
        const int t2 = (lane & 3) * 2;
        #pragma unroll
        for (int ni = 0; ni < 4; ni++) {
            int c = n0 + ni * 8 + t2;
            *(float2*)&sS[(m0 + g) * 66 + c]     = make_float2(acc[ni][0], acc[ni][1]);
            *(float2*)&sS[(m0 + 8 + g) * 66 + c] = make_float2(acc[ni][2], acc[ni][3]);
        }
    }
    __syncthreads();

    // ---- Phase 4: softmax (4 threads/row), UNIFORM across all 64 rows ----
    {
        const int r  = tid >> 2;
        const int c0 = (tid & 3) * 16;
        const int rr = (r < N_TOK) ? r : 0;   // clamp table row for padded rows
        const int ww = b & (NWMASK - 1);
        const float* pbr = g_pb + h * NN + rr * N_TOK;
        const float* mr  = mask + (size_t)ww * NN + rr * N_TOK;
        float vals[16];
        float mx = -1e30f;
        #pragma unroll
        for (int i = 0; i < 16; i++) {
            int m = c0 + i;
            float v = -1e30f;
            if (m < N_TOK) v = sS[r * 66 + m] + pbr[m] + mr[m];
            vals[i] = v;
            mx = fmaxf(mx, v);
        }
        mx = fmaxf(mx, __shfl_xor_sync(0xffffffff, mx, 1));
        mx = fmaxf(mx, __shfl_xor_sync(0xffffffff, mx, 2));
        float sum = 0.f;
        #pragma unroll
        for (int i = 0; i < 16; i++) {
            float e = (c0 + i < N_TOK) ? __expf(vals[i] - mx) : 0.f;
            vals[i] = e;
            sum += e;
        }
        sum += __shfl_xor_sync(0xffffffff, sum, 1);
        sum += __shfl_xor_sync(0xffffffff, sum, 2);
        float inv = 1.f / sum;   // padded rows: garbage but finite; rows >= N_TOK never stored
        #pragma unroll
        for (int i = 0; i < 16; i += 2) {
            __nv_bfloat16 h0, l0, h1, l1;
            split1(vals[i] * inv, h0, l0);
            split1(vals[i + 1] * inv, h1, l1);
            *(uint32_t*)&sPh[r * 72 + c0 + i] = pack2(h0, h1);
            *(uint32_t*)&sPl[r * 72 + c0 + i] = pack2(l0, l1);
        }
    }
    __syncthreads();

    // ---- Phase 5: O = P @ V via 3-term split-bf16 MMA; split-store output ----
    {
        const int m0  = (w & 3) * 16;
        const int n0  = (w >> 2) * 16;     // 0 or 16 (of 32 dims)
        const int l15 = lane & 15;
        const int lhi8 = (lane >> 4) * 8;
        float acc[2][4];
        #pragma unroll
        for (int ni = 0; ni < 2; ni++)
            #pragma unroll
            for (int r = 0; r < 4; r++) acc[ni][r] = 0.f;

        #pragma unroll
        for (int ks = 0; ks < 64; ks += 16) {
            uint32_t ah[4], al[4];
            uint32_t dsA = (uint32_t)(ATT_PH) + (uint32_t)((m0 + l15) * 72 + ks + lhi8) * 2;
            ldsm_x4(ah, smb + dsA);
            ldsm_x4(al, smb + dsA + (ATT_PL - ATT_PH));
            #pragma unroll
            for (int ni = 0; ni < 2; ni++) {
                uint32_t bh[2], bl[2];
                uint32_t dsB = (uint32_t)(ATT_VH) + (uint32_t)((ks + l15) * 40 + n0 + ni * 8) * 2;
                ldsm_x2t(bh, smb + dsB);
                ldsm_x2t(bl, smb + dsB + (ATT_VL - ATT_VH));
                mma_bf16(acc[ni], ah, bh);
                mma_bf16(acc[ni], ah, bl);
                mma_bf16(acc[ni], al, bh);
            }
        }
        const int g  = lane >> 2;
        const int t2 = (lane & 3) * 2;
        #pragma unroll
        for (int ni = 0; ni < 2; ni++) {
            int col  = h * HD + n0 + ni * 8 + t2;
            int row0 = m0 + g, row1 = m0 + 8 + g;
            if (row0 < N_TOK) {
                size_t o = ((size_t)b * N_TOK + row0) * C_DIM + col;
                __nv_bfloat16 h0, l0, h1, l1;
                split1(acc[ni][0], h0, l0);
                split1(acc[ni][1], h1, l1);
                *(uint32_t*)(g_aoh + o) = pack2(h0, h1);
                *(uint32_t*)(g_aol + o) = pack2(l0, l1);
            }
            if (row1 < N_TOK) {
                size_t o = ((size_t)b * N_TOK + row1) * C_DIM + col;
                __nv_bfloat16 h0, l0, h1, l1;
                split1(acc[ni][2], h0, l0);
                split1(acc[ni][3], h1, l1);
                *(uint32_t*)(g_aoh + o) = pack2(h0, h1);
                *(uint32_t*)(g_aol + o) = pack2(l0, l1);
            }
        }
    }
}

// ---------------------------------------------------------------------------
// Launch
// ---------------------------------------------------------------------------
extern "C" void kernel_launch(void* const* d_in, const int* in_sizes, int n_in,
                              void* d_out, int out_size) {
    const float* x           = (const float*)d_in[0];
    const float* mask        = (const float*)d_in[1];
    const float* qkv_w       = (const float*)d_in[2];
    const float* q_bias      = (const float*)d_in[3];
    const float* v_bias      = (const float*)d_in[4];
    const float* logit_scale = (const float*)d_in[5];
    const float* rpe_w1      = (const float*)d_in[6];
    const float* rpe_b1      = (const float*)d_in[7];
    const float* rpe_w2      = (const float*)d_in[8];
    const float* proj_w      = (const float*)d_in[9];
    const float* proj_b      = (const float*)d_in[10];
    float* out = (float*)d_out;

    cudaFuncSetAttribute(qkv_gemm_kernel,
                         cudaFuncAttributeMaxDynamicSharedMemorySize, SMEM_BYTES);
    cudaFuncSetAttribute(proj_gemm_kernel,
                         cudaFuncAttributeMaxDynamicSharedMemorySize, SMEM_BYTES);

    __nv_bfloat16 *xh, *xl, *qwh, *qwl, *pwh, *pwl;
    cudaGetSymbolAddress((void**)&xh,  g_xh);
    cudaGetSymbolAddress((void**)&xl,  g_xl);
    cudaGetSymbolAddress((void**)&qwh, g_qwh);
    cudaGetSymbolAddress((void**)&qwl, g_qwl);
    cudaGetSymbolAddress((void**)&pwh, g_pwh);
    cudaGetSymbolAddress((void**)&pwl, g_pwl);

    setup_kernel<<<1, 256>>>(rpe_w1, rpe_b1, rpe_w2, q_bias, v_bias);

    {
        int n4 = M_ROWS * C_DIM / 4;
        split_kernel<<<(n4 + 255) / 256, 256>>>(x, xh, xl, n4);
    }
    {
        int n4 = C_DIM * QKV_N / 4;
        split_kernel<<<(n4 + 255) / 256, 256>>>(qkv_w, qwh, qwl, n4);
    }
    {
        int n4 = C_DIM * C_DIM / 4;
        split_kernel<<<(n4 + 255) / 256, 256>>>(proj_w, pwh, pwl, n4);
    }

    qkv_gemm_kernel<<<dim3(QKV_N / 128, M_ROWS / 128), 256, SMEM_BYTES>>>();

    attn_kernel<<<BWIN * N_HEADS, 256>>>(mask, logit_scale);

    proj_gemm_kernel<<<dim3(C_DIM / 128, M_ROWS / 128), 256, SMEM_BYTES>>>(proj_b, out);
}

// round 11
// speedup vs baseline: 2.2787x; 1.0528x over previous
#include <cuda_runtime.h>
#include <cuda_bf16.h>
#include <math.h>
#include <stdint.h>

// ---------------------------------------------------------------------------
// Problem constants
// ---------------------------------------------------------------------------
#define BWIN    2048
#define N_TOK   49
#define C_DIM   512
#define N_HEADS 16
#define HD      32
#define QKV_N   1536
#define M_ROWS  (BWIN * N_TOK)     // 100352 = 784 * 128
#define NN      (N_TOK * N_TOK)    // 2401
#define NWMASK  64

// ---------------------------------------------------------------------------
// Scratch (static device globals)
// ---------------------------------------------------------------------------
__device__ float g_qkv[(size_t)M_ROWS * QKV_N];          // fp32 qkv
__device__ __nv_bfloat16 g_xh[(size_t)M_ROWS * C_DIM];   // x split hi
__device__ __nv_bfloat16 g_xl[(size_t)M_ROWS * C_DIM];   // x split lo
__device__ __nv_bfloat16 g_aoh[(size_t)M_ROWS * C_DIM];  // attn out split hi
__device__ __nv_bfloat16 g_aol[(size_t)M_ROWS * C_DIM];  // attn out split lo
__device__ __nv_bfloat16 g_qwh[C_DIM * QKV_N];
__device__ __nv_bfloat16 g_qwl[C_DIM * QKV_N];
__device__ __nv_bfloat16 g_pwh[C_DIM * C_DIM];
__device__ __nv_bfloat16 g_pwl[C_DIM * C_DIM];
__device__ float g_pb [N_HEADS * NN];
__device__ float g_qkvbias[QKV_N];

// ---------------------------------------------------------------------------
// Helpers
// ---------------------------------------------------------------------------
__device__ __forceinline__ uint32_t pack2(__nv_bfloat16 a, __nv_bfloat16 b) {
    __nv_bfloat162 v; v.x = a; v.y = b;
    return *(uint32_t*)&v;
}
__device__ __forceinline__ void split1(float v, __nv_bfloat16& h, __nv_bfloat16& l) {
    h = __float2bfloat16(v);
    l = __float2bfloat16(v - __bfloat162float(h));
}

__device__ __forceinline__ void mma_bf16(float d[4],
                                         const uint32_t a[4],
                                         const uint32_t b[2]) {
    asm volatile(
        "mma.sync.aligned.m16n8k16.row.col.f32.bf16.bf16.f32 "
        "{%0,%1,%2,%3}, {%4,%5,%6,%7}, {%8,%9}, {%0,%1,%2,%3};\n"
        : "+f"(d[0]), "+f"(d[1]), "+f"(d[2]), "+f"(d[3])
        : "r"(a[0]), "r"(a[1]), "r"(a[2]), "r"(a[3]), "r"(b[0]), "r"(b[1]));
}
__device__ __forceinline__ void ldsm_x4(uint32_t r[4], uint32_t addr) {
    asm volatile("ldmatrix.sync.aligned.m8n8.x4.shared.b16 {%0,%1,%2,%3}, [%4];\n"
                 : "=r"(r[0]), "=r"(r[1]), "=r"(r[2]), "=r"(r[3]) : "r"(addr));
}
__device__ __forceinline__ void ldsm_x2t(uint32_t r[2], uint32_t addr) {
    asm volatile("ldmatrix.sync.aligned.m8n8.x2.trans.shared.b16 {%0,%1}, [%2];\n"
                 : "=r"(r[0]), "=r"(r[1]) : "r"(addr));
}
__device__ __forceinline__ void cp16(uint32_t dst, const void* src) {
    asm volatile("cp.async.cg.shared.global [%0], [%1], 16;\n" :: "r"(dst), "l"(src));
}
__device__ __forceinline__ void cp_commit() { asm volatile("cp.async.commit_group;\n"); }
__device__ __forceinline__ void cp_wait1()  { asm volatile("cp.async.wait_group 1;\n" ::: "memory"); }

// ---------------------------------------------------------------------------
// Split kernel: fp32 -> bf16 hi/lo (vectorized x4)
// ---------------------------------------------------------------------------
__global__ void split_kernel(const float* __restrict__ src,
                             __nv_bfloat16* __restrict__ dh,
                             __nv_bfloat16* __restrict__ dl, int n4) {
    int i = blockIdx.x * blockDim.x + threadIdx.x;
    if (i >= n4) return;
    float4 v = ((const float4*)src)[i];
    __nv_bfloat16 hx, lx, hy, ly, hz, lz, hw, lw;
    split1(v.x, hx, lx); split1(v.y, hy, ly);
    split1(v.z, hz, lz); split1(v.w, hw, lw);
    uint2 ph, pl;
    ph.x = pack2(hx, hy); ph.y = pack2(hz, hw);
    pl.x = pack2(lx, ly); pl.y = pack2(lz, lw);
    ((uint2*)dh)[i] = ph;
    ((uint2*)dl)[i] = pl;
}

// ---------------------------------------------------------------------------
// Kernel 1: RPE table MLP + bias gather + qkv bias vector
// ---------------------------------------------------------------------------
__device__ __forceinline__ float coord_feat(int x) {
    float xs = (float)x * (8.0f / 121.0f);
    float v = log1pf(fabsf(xs)) * 0.48089834696298783f; // 1/ln(8)
    return copysignf(v, xs);
}

__global__ void setup_kernel(const float* __restrict__ rpe_w1,
                             const float* __restrict__ rpe_b1,
                             const float* __restrict__ rpe_w2,
                             const float* __restrict__ q_bias,
                             const float* __restrict__ v_bias) {
    __shared__ float sbt[169 * N_HEADS];
    const int tid = threadIdx.x; // 256 threads

    if (tid < 169) {
        int a = tid / 13, b = tid % 13;
        float c0 = coord_feat(b - 6);
        float c1 = coord_feat(a - 6);
        float acc[N_HEADS];
        #pragma unroll
        for (int t = 0; t < N_HEADS; t++) acc[t] = 0.f;
        for (int j = 0; j < 512; j++) {
            float h1 = fmaf(c0, rpe_w1[j], fmaf(c1, rpe_w1[512 + j], rpe_b1[j]));
            h1 = fmaxf(h1, 0.f);
            const float* w2 = rpe_w2 + j * N_HEADS;
            #pragma unroll
            for (int t = 0; t < N_HEADS; t++) acc[t] = fmaf(h1, w2[t], acc[t]);
        }
        #pragma unroll
        for (int t = 0; t < N_HEADS; t++) sbt[tid * N_HEADS + t] = acc[t];
    }

    for (int c = tid; c < QKV_N; c += 256) {
        float v = 0.f;
        if (c < 512)        v = q_bias[c];
        else if (c >= 1024) v = v_bias[c - 1024];
        g_qkvbias[c] = v;
    }
    __syncthreads();

    for (int idx = tid; idx < N_HEADS * NN; idx += 256) {
        int h   = idx / NN;
        int rem = idx % NN;
        int n = rem / N_TOK, m = rem % N_TOK;
        int di = (n / 7) - (m / 7);
        int dj = (n % 7) - (m % 7);
        int r = (dj + 6) * 13 + (di + 6);
        float bt = sbt[r * N_HEADS + h];
        g_pb[idx] = 16.f / (1.f + expf(-bt));
    }
}

// ---------------------------------------------------------------------------
// Pipelined split-bf16 tensor-core GEMM, v2: 128 threads = 4 warps,
// warp tile 64x64 (2x2 warp grid over the 128x128 block), BK=32.
// A-fragment reuse 8x (was 4x) => smem traffic/MMA drops 128B -> 83B.
// 2 CTAs/SM (regs ~190/thread * 128 thr * 2 < 64K RF).
// ---------------------------------------------------------------------------
#define SA_STR 40
#define SB_STR 136
#define ASIZE (128 * SA_STR)
#define BSIZE (32 * SB_STR)
#define SMEM_BYTES ((2 * (2 * ASIZE + 2 * BSIZE)) * 2)  // 75776 B

__device__ __forceinline__ void gemm_issue(
    int it, int buf, int iters, int tid,
    const __nv_bfloat16* Ah, const __nv_bfloat16* Al,
    const __nv_bfloat16* Bh, const __nv_bfloat16* Bl,
    size_t Abase, int nblk, int N, int K,
    uint32_t sAh32, uint32_t sAl32, uint32_t sBh32, uint32_t sBl32)
{
    if (it < iters) {
        const int k0 = it * 32;
        const uint32_t aoff = (uint32_t)buf * (ASIZE * 2);
        const uint32_t boff = (uint32_t)buf * (BSIZE * 2);
        // A tile: 128 rows x 32 k x 2B = 8192B per h/l = 512 chunks of 16B
        #pragma unroll
        for (int p = 0; p < 4; p++) {
            int c = tid + p * 128;
            int row = c >> 2, seg = (c & 3) * 8;
            size_t go = Abase + (size_t)row * K + k0 + seg;
            uint32_t ds = (uint32_t)(row * SA_STR + seg) * 2;
            cp16(sAh32 + aoff + ds, Ah + go);
            cp16(sAl32 + aoff + ds, Al + go);
        }
        // B tile: 32 rows x 128 n x 2B = 8192B per h/l = 512 chunks
        #pragma unroll
        for (int p = 0; p < 4; p++) {
            int c = tid + p * 128;
            int row = c >> 4, seg = (c & 15) * 8;
            size_t go = (size_t)(k0 + row) * N + nblk + seg;
            uint32_t ds = (uint32_t)(row * SB_STR + seg) * 2;
            cp16(sBh32 + boff + ds, Bh + go);
            cp16(sBl32 + boff + ds, Bl + go);
        }
    }
    cp_commit();
}

__device__ __forceinline__ void gemm_core(
    const __nv_bfloat16* __restrict__ Ah, const __nv_bfloat16* __restrict__ Al,
    const __nv_bfloat16* __restrict__ Bh, const __nv_bfloat16* __restrict__ Bl,
    const float* __restrict__ bias, float* __restrict__ C, int N, int K)
{
    extern __shared__ __nv_bfloat16 smem[];
    __nv_bfloat16* sAh = smem;
    __nv_bfloat16* sAl = sAh + 2 * ASIZE;
    __nv_bfloat16* sBh = sAl + 2 * ASIZE;
    __nv_bfloat16* sBl = sBh + 2 * BSIZE;

    const int tid  = threadIdx.x;          // 128 threads
    const int bm   = blockIdx.y, bn = blockIdx.x;
    const int lane = tid & 31;
    const int w    = tid >> 5;              // 0..3
    const int wm   = (w >> 1) * 64;         // 0 or 64
    const int wn   = (w & 1) * 64;          // 0 or 64
    const int l15  = lane & 15;
    const int lhi8 = (lane >> 4) * 8;

    const size_t Abase = (size_t)bm * 128 * K;
    const int nblk = bn * 128;

    const uint32_t sAh32 = (uint32_t)__cvta_generic_to_shared(sAh);
    const uint32_t sAl32 = (uint32_t)__cvta_generic_to_shared(sAl);
    const uint32_t sBh32 = (uint32_t)__cvta_generic_to_shared(sBh);
    const uint32_t sBl32 = (uint32_t)__cvta_generic_to_shared(sBl);

    float acc[4][8][4];                     // 4 mi x 8 ni x 4
    #pragma unroll
    for (int mi = 0; mi < 4; mi++)
        #pragma unroll
        for (int ni = 0; ni < 8; ni++)
            #pragma unroll
            for (int r = 0; r < 4; r++) acc[mi][ni][r] = 0.f;

    const int iters = K / 32;
    gemm_issue(0, 0, iters, tid, Ah, Al, Bh, Bl, Abase, nblk, N, K, sAh32, sAl32, sBh32, sBl32);
    gemm_issue(1, 1, iters, tid, Ah, Al, Bh, Bl, Abase, nblk, N, K, sAh32, sAl32, sBh32, sBl32);

    for (int it = 0; it < iters; it++) {
        const int buf = it & 1;
        cp_wait1();
        __syncthreads();

        const uint32_t aoff = (uint32_t)buf * (ASIZE * 2);
        const uint32_t boff = (uint32_t)buf * (BSIZE * 2);

        #pragma unroll
        for (int ks = 0; ks < 32; ks += 16) {
            uint32_t bh[8][2], bl[8][2];
            #pragma unroll
            for (int ni = 0; ni < 8; ni++) {
                uint32_t ds = (uint32_t)((ks + l15) * SB_STR + wn + ni * 8) * 2;
                ldsm_x2t(bh[ni], sBh32 + boff + ds);
                ldsm_x2t(bl[ni], sBl32 + boff + ds);
            }
            #pragma unroll
            for (int mi = 0; mi < 4; mi++) {
                uint32_t ds = (uint32_t)((wm + mi * 16 + l15) * SA_STR + ks + lhi8) * 2;
                uint32_t ah[4], al[4];
                ldsm_x4(ah, sAh32 + aoff + ds);
                ldsm_x4(al, sAl32 + aoff + ds);
                #pragma unroll
                for (int ni = 0; ni < 8; ni++) {
                    mma_bf16(acc[mi][ni], ah, bh[ni]);
                    mma_bf16(acc[mi][ni], ah, bl[ni]);
                    mma_bf16(acc[mi][ni], al, bh[ni]);
                }
            }
        }
        __syncthreads();
        gemm_issue(it + 2, buf, iters, tid, Ah, Al, Bh, Bl, Abase, nblk, N, K,
                   sAh32, sAl32, sBh32, sBl32);
    }

    const int g  = lane >> 2;
    const int t2 = (lane & 3) * 2;
    #pragma unroll
    for (int mi = 0; mi < 4; mi++) {
        int row = bm * 128 + wm + mi * 16 + g;
        #pragma unroll
        for (int ni = 0; ni < 8; ni++) {
            int col = bn * 128 + wn + ni * 8 + t2;
            float b0 = bias[col], b1 = bias[col + 1];
            float2 o0 = make_float2(acc[mi][ni][0] + b0, acc[mi][ni][1] + b1);
            float2 o1 = make_float2(acc[mi][ni][2] + b0, acc[mi][ni][3] + b1);
            *(float2*)(C + (size_t)row * N + col)       = o0;
            *(float2*)(C + (size_t)(row + 8) * N + col) = o1;
        }
    }
}

__global__ void __launch_bounds__(128, 2)
qkv_gemm_kernel() {
    gemm_core(g_xh, g_xl, g_qwh, g_qwl, g_qkvbias, g_qkv, QKV_N, C_DIM);
}

__global__ void __launch_bounds__(128, 2)
proj_gemm_kernel(const float* __restrict__ proj_b, float* __restrict__ out) {
    gemm_core(g_aoh, g_aol, g_pwh, g_pwl, proj_b, out, C_DIM, C_DIM);
}

// ---------------------------------------------------------------------------
// Kernel 3: tensor-core attention per (window, head) — unchanged (validated R10)
// ---------------------------------------------------------------------------
#define ATT_QH  0
#define ATT_QL  5120
#define ATT_KTH 10240
#define ATT_KTL 14848
#define ATT_VH  19456
#define ATT_VL  24576
#define ATT_SS  29696
#define ATT_TOT (29696 + 64 * 66 * 4)   // 46592 B
#define ATT_PH  0
#define ATT_PL  9216

__global__ void __launch_bounds__(256, 2)
attn_kernel(const float* __restrict__ mask, const float* __restrict__ logit_scale) {
    const int b = blockIdx.x >> 4;
    const int h = blockIdx.x & 15;
    const int tid  = threadIdx.x;
    const int lane = tid & 31;
    const int w    = tid >> 5;

    __shared__ __align__(16) char sm[ATT_TOT];
    __nv_bfloat16* sQh  = (__nv_bfloat16*)(sm + ATT_QH);
    __nv_bfloat16* sQl  = (__nv_bfloat16*)(sm + ATT_QL);
    __nv_bfloat16* sKth = (__nv_bfloat16*)(sm + ATT_KTH);
    __nv_bfloat16* sKtl = (__nv_bfloat16*)(sm + ATT_KTL);
    __nv_bfloat16* sVh  = (__nv_bfloat16*)(sm + ATT_VH);
    __nv_bfloat16* sVl  = (__nv_bfloat16*)(sm + ATT_VL);
    __nv_bfloat16* sPh  = (__nv_bfloat16*)(sm + ATT_PH);
    __nv_bfloat16* sPl  = (__nv_bfloat16*)(sm + ATT_PL);
    float* sS = (float*)(sm + ATT_SS);
    const uint32_t smb = (uint32_t)__cvta_generic_to_shared(sm);

    // ---- Phase 1: load q,k fp32 into staging; v split directly ----
    const float* base = g_qkv + (size_t)b * N_TOK * QKV_N + h * HD;
    #pragma unroll
    for (int p = 0; p < 8; p++) {
        int idx = tid + p * 256;
        int r = idx >> 5, d = idx & 31;
        float qv = 0.f, kv = 0.f, vv = 0.f;
        if (r < N_TOK) {
            const float* pp = base + (size_t)r * QKV_N + d;
            qv = pp[0]; kv = pp[512]; vv = pp[1024];
        }
        sS[r * 66 + d]      = qv;
        sS[r * 66 + 32 + d] = kv;
        __nv_bfloat16 vh, vl;
        split1(vv, vh, vl);
        sVh[r * 40 + d] = vh;
        sVl[r * 40 + d] = vl;
    }
    __syncthreads();

    // ---- Phase 2: normalize rows (4 threads/row, uniform), split Q / K^T ----
    {
        const int r  = tid >> 2;
        const int qd = (tid & 3) * 8;
        float qv[8], kv[8];
        float sq = 0.f, sk = 0.f;
        #pragma unroll
        for (int j = 0; j < 8; j++) {
            qv[j] = sS[r * 66 + qd + j];
            kv[j] = sS[r * 66 + 32 + qd + j];
            sq = fmaf(qv[j], qv[j], sq);
            sk = fmaf(kv[j], kv[j], sk);
        }
        sq += __shfl_xor_sync(0xffffffff, sq, 1);
        sq += __shfl_xor_sync(0xffffffff, sq, 2);
        sk += __shfl_xor_sync(0xffffffff, sk, 1);
        sk += __shfl_xor_sync(0xffffffff, sk, 2);
        float hs  = __expf(fminf(logit_scale[h], 4.605170185988091f));
        float qsc = rsqrtf(fmaxf(sq, 1e-12f)) * hs;
        float ksc = rsqrtf(fmaxf(sk, 1e-12f));
        #pragma unroll
        for (int j = 0; j < 8; j += 2) {
            __nv_bfloat16 h0, l0, h1, l1;
            split1(qv[j] * qsc, h0, l0);
            split1(qv[j + 1] * qsc, h1, l1);
            *(uint32_t*)&sQh[r * 40 + qd + j] = pack2(h0, h1);
            *(uint32_t*)&sQl[r * 40 + qd + j] = pack2(l0, l1);
        }
        #pragma unroll
        for (int j = 0; j < 8; j++) {
            __nv_bfloat16 kh, kl;
            split1(kv[j] * ksc, kh, kl);
            sKth[(qd + j) * 72 + r] = kh;
            sKtl[(qd + j) * 72 + r] = kl;
        }
    }
    __syncthreads();

    // ---- Phase 3: S = Qn @ Kn^T via 3-term split-bf16 MMA ----
    {
        const int m0  = (w & 3) * 16;
        const int n0  = (w >> 2) * 32;
        const int l15 = lane & 15;
        const int lhi8 = (lane >> 4) * 8;
        float acc[4][4];
        #pragma unroll
        for (int ni = 0; ni < 4; ni++)
            #pragma unroll
            for (int r = 0; r < 4; r++) acc[ni][r] = 0.f;

        #pragma unroll
        for (int ks = 0; ks < 32; ks += 16) {
            uint32_t ah[4], al[4];
            uint32_t dsA = (uint32_t)(ATT_QH) + (uint32_t)((m0 + l15) * 40 + ks + lhi8) * 2;
            ldsm_x4(ah, smb + dsA);
            ldsm_x4(al, smb + dsA + (ATT_QL - ATT_QH));
            #pragma unroll
            for (int ni = 0; ni < 4; ni++) {
                uint32_t bh[2], bl[2];
                uint32_t dsB = (uint32_t)(ATT_KTH) + (uint32_t)((ks + l15) * 72 + n0 + ni * 8) * 2;
                ldsm_x2t(bh, smb + dsB);
                ldsm_x2t(bl, smb + dsB + (ATT_KTL - ATT_KTH));
                mma_bf16(acc[ni], ah, bh);
                mma_bf16(acc[ni], ah, bl);
                mma_bf16(acc[ni], al, bh);
            }
        }
        const int g  = lane >> 2;
        const int t2 = (lane & 3) * 2;
        #pragma unroll
        for (int ni = 0; ni < 4; ni++) {
            int c = n0 + ni * 8 + t2;
            *(float2*)&sS[(m0 + g) * 66 + c]     = make_float2(acc[ni][0], acc[ni][1]);
            *(float2*)&sS[(m0 + 8 + g) * 66 + c] = make_float2(acc[ni][2], acc[ni][3]);
        }
    }
    __syncthreads();

    // ---- Phase 4: softmax (4 threads/row), UNIFORM across all 64 rows ----
    {
        const int r  = tid >> 2;
        const int c0 = (tid & 3) * 16;
        const int rr = (r < N_TOK) ? r : 0;
        const int ww = b & (NWMASK - 1);
        const float* pbr = g_pb + h * NN + rr * N_TOK;
        const float* mr  = mask + (size_t)ww * NN + rr * N_TOK;
        float vals[16];
        float mx = -1e30f;
        #pragma unroll
        for (int i = 0; i < 16; i++) {
            int m = c0 + i;
            float v = -1e30f;
            if (m < N_TOK) v = sS[r * 66 + m] + pbr[m] + mr[m];
            vals[i] = v;
            mx = fmaxf(mx, v);
        }
        mx = fmaxf(mx, __shfl_xor_sync(0xffffffff, mx, 1));
        mx = fmaxf(mx, __shfl_xor_sync(0xffffffff, mx, 2));
        float sum = 0.f;
        #pragma unroll
        for (int i = 0; i < 16; i++) {
            float e = (c0 + i < N_TOK) ? __expf(vals[i] - mx) : 0.f;
            vals[i] = e;
            sum += e;
        }
        sum += __shfl_xor_sync(0xffffffff, sum, 1);
        sum += __shfl_xor_sync(0xffffffff, sum, 2);
        float inv = 1.f / sum;
        #pragma unroll
        for (int i = 0; i < 16; i += 2) {
            __nv_bfloat16 h0, l0, h1, l1;
            split1(vals[i] * inv, h0, l0);
            split1(vals[i + 1] * inv, h1, l1);
            *(uint32_t*)&sPh[r * 72 + c0 + i] = pack2(h0, h1);
            *(uint32_t*)&sPl[r * 72 + c0 + i] = pack2(l0, l1);
        }
    }
    __syncthreads();

    // ---- Phase 5: O = P @ V via 3-term split-bf16 MMA; split-store output ----
    {
        const int m0  = (w & 3) * 16;
        const int n0  = (w >> 2) * 16;
        const int l15 = lane & 15;
        const int lhi8 = (lane >> 4) * 8;
        float acc[2][4];
        #pragma unroll
        for (int ni = 0; ni < 2; ni++)
            #pragma unroll
            for (int r = 0; r < 4; r++) acc[ni][r] = 0.f;

        #pragma unroll
        for (int ks = 0; ks < 64; ks += 16) {
            uint32_t ah[4], al[4];
            uint32_t dsA = (uint32_t)(ATT_PH) + (uint32_t)((m0 + l15) * 72 + ks + lhi8) * 2;
            ldsm_x4(ah, smb + dsA);
            ldsm_x4(al, smb + dsA + (ATT_PL - ATT_PH));
            #pragma unroll
            for (int ni = 0; ni < 2; ni++) {
                uint32_t bh[2], bl[2];
                uint32_t dsB = (uint32_t)(ATT_VH) + (uint32_t)((ks + l15) * 40 + n0 + ni * 8) * 2;
                ldsm_x2t(bh, smb + dsB);
                ldsm_x2t(bl, smb + dsB + (ATT_VL - ATT_VH));
                mma_bf16(acc[ni], ah, bh);
                mma_bf16(acc[ni], ah, bl);
                mma_bf16(acc[ni], al, bh);
            }
        }
        const int g  = lane >> 2;
        const int t2 = (lane & 3) * 2;
        #pragma unroll
        for (int ni = 0; ni < 2; ni++) {
            int col  = h * HD + n0 + ni * 8 + t2;
            int row0 = m0 + g, row1 = m0 + 8 + g;
            if (row0 < N_TOK) {
                size_t o = ((size_t)b * N_TOK + row0) * C_DIM + col;
                __nv_bfloat16 h0, l0, h1, l1;
                split1(acc[ni][0], h0, l0);
                split1(acc[ni][1], h1, l1);
                *(uint32_t*)(g_aoh + o) = pack2(h0, h1);
                *(uint32_t*)(g_aol + o) = pack2(l0, l1);
            }
            if (row1 < N_TOK) {
                size_t o = ((size_t)b * N_TOK + row1) * C_DIM + col;
                __nv_bfloat16 h0, l0, h1, l1;
                split1(acc[ni][2], h0, l0);
                split1(acc[ni][3], h1, l1);
                *(uint32_t*)(g_aoh + o) = pack2(h0, h1);
                *(uint32_t*)(g_aol + o) = pack2(l0, l1);
            }
        }
    }
}

// ---------------------------------------------------------------------------
// Launch
// ---------------------------------------------------------------------------
extern "C" void kernel_launch(void* const* d_in, const int* in_sizes, int n_in,
                              void* d_out, int out_size) {
    const float* x           = (const float*)d_in[0];
    const float* mask        = (const float*)d_in[1];
    const float* qkv_w       = (const float*)d_in[2];
    const float* q_bias      = (const float*)d_in[3];
    const float* v_bias      = (const float*)d_in[4];
    const float* logit_scale = (const float*)d_in[5];
    const float* rpe_w1      = (const float*)d_in[6];
    const float* rpe_b1      = (const float*)d_in[7];
    const float* rpe_w2      = (const float*)d_in[8];
    const float* proj_w      = (const float*)d_in[9];
    const float* proj_b      = (const float*)d_in[10];
    float* out = (float*)d_out;

    cudaFuncSetAttribute(qkv_gemm_kernel,
                         cudaFuncAttributeMaxDynamicSharedMemorySize, SMEM_BYTES);
    cudaFuncSetAttribute(proj_gemm_kernel,
                         cudaFuncAttributeMaxDynamicSharedMemorySize, SMEM_BYTES);

    __nv_bfloat16 *xh, *xl, *qwh, *qwl, *pwh, *pwl;
    cudaGetSymbolAddress((void**)&xh,  g_xh);
    cudaGetSymbolAddress((void**)&xl,  g_xl);
    cudaGetSymbolAddress((void**)&qwh, g_qwh);
    cudaGetSymbolAddress((void**)&qwl, g_qwl);
    cudaGetSymbolAddress((void**)&pwh, g_pwh);
    cudaGetSymbolAddress((void**)&pwl, g_pwl);

    setup_kernel<<<1, 256>>>(rpe_w1, rpe_b1, rpe_w2, q_bias, v_bias);

    {
        int n4 = M_ROWS * C_DIM / 4;
        split_kernel<<<(n4 + 255) / 256, 256>>>(x, xh, xl, n4);
    }
    {
        int n4 = C_DIM * QKV_N / 4;
        split_kernel<<<(n4 + 255) / 256, 256>>>(qkv_w, qwh, qwl, n4);
    }
    {
        int n4 = C_DIM * C_DIM / 4;
        split_kernel<<<(n4 + 255) / 256, 256>>>(proj_w, pwh, pwl, n4);
    }

    // QKV: [100352,512] @ [512,1536], 128-thread blocks
    qkv_gemm_kernel<<<dim3(QKV_N / 128, M_ROWS / 128), 128, SMEM_BYTES>>>();

    attn_kernel<<<BWIN * N_HEADS, 256>>>(mask, logit_scale);

    // proj: [100352,512] @ [512,512] -> d_out
    proj_gemm_kernel<<<dim3(C_DIM / 128, M_ROWS / 128), 128, SMEM_BYTES>>>(proj_b, out);
}